// round 7
// baseline (speedup 1.0000x reference)
#include <cuda_runtime.h>

#define N_NODES 100000
#define N_EDGES 1600000
#define HID 128
#define SCAN_B 1024
#define NB_SCAN ((N_NODES + SCAN_B - 1) / SCAN_B)   // 98

typedef unsigned long long u64;

// Scratch (no cudaMalloc allowed).
__device__ __align__(16) float g_A[(size_t)N_NODES * HID];   // layer-2 GEMM output (M2)
__device__ __align__(16) float g_B[(size_t)N_NODES * HID];   // layer-3 GEMM output (M3)
__device__ __align__(16) float g_XA[(size_t)N_NODES * 5];    // aggregated raw input
__device__ __align__(16) float g_dinv[N_NODES];
__device__ int   g_cnt[N_NODES];
__device__ int   g_off[N_NODES];     // scan result; k_fill bumps it to segment END
__device__ int   g_bsum[NB_SCAN];
__device__ int   g_boff[NB_SCAN];
__device__ int   g_srcs[N_EDGES];
__device__ float g_wsrc[N_EDGES];

#define FFMA2(acc, a, b) asm("fma.rn.f32x2 %0, %1, %2, %0;" : "+l"(acc) : "l"(a), "l"(b))
union F2U { u64 u; float2 f; };

// ---------------- CSR build ----------------
__global__ void k_zero() {
    int i = blockIdx.x * blockDim.x + threadIdx.x;
    if (i < N_NODES) g_cnt[i] = 0;
}

__global__ void k_deg_count(const int* __restrict__ dst) {
    int e = blockIdx.x * blockDim.x + threadIdx.x;
    if (e < N_EDGES) atomicAdd(&g_cnt[dst[e]], 1);
}

// per-block sums of g_cnt + fused dinv computation
__global__ __launch_bounds__(SCAN_B) void k_bsum() {
    __shared__ int sh[SCAN_B];
    int t = threadIdx.x;
    int i = blockIdx.x * SCAN_B + t;
    int c = 0;
    if (i < N_NODES) {
        c = g_cnt[i];
        g_dinv[i] = rsqrtf((float)(c + 1));   // +1 self loop
    }
    sh[t] = c;
    __syncthreads();
    #pragma unroll
    for (int off = SCAN_B / 2; off > 0; off >>= 1) {
        if (t < off) sh[t] += sh[t + off];
        __syncthreads();
    }
    if (t == 0) g_bsum[blockIdx.x] = sh[0];
}

__global__ __launch_bounds__(128) void k_bscan() {
    __shared__ int sh[128];
    int t = threadIdx.x;
    sh[t] = (t < NB_SCAN) ? g_bsum[t] : 0;
    __syncthreads();
    #pragma unroll
    for (int off = 1; off < 128; off <<= 1) {
        int v = sh[t];
        int a = (t >= off) ? sh[t - off] : 0;
        __syncthreads();
        sh[t] = v + a;
        __syncthreads();
    }
    if (t < NB_SCAN) g_boff[t] = (t == 0) ? 0 : sh[t - 1];
}

__global__ __launch_bounds__(SCAN_B) void k_boff() {
    __shared__ int sh[SCAN_B];
    int t = threadIdx.x;
    int i = blockIdx.x * SCAN_B + t;
    int v = (i < N_NODES) ? g_cnt[i] : 0;
    sh[t] = v;
    __syncthreads();
    #pragma unroll
    for (int off = 1; off < SCAN_B; off <<= 1) {
        int cur = sh[t];
        int a = (t >= off) ? sh[t - off] : 0;
        __syncthreads();
        sh[t] = cur + a;
        __syncthreads();
    }
    if (i < N_NODES) g_off[i] = g_boff[blockIdx.x] + sh[t] - v;   // exclusive
}

// destructive fill: g_off[d] ends at segment END; start recovered as end - cnt
__global__ void k_fill(const int* __restrict__ src, const int* __restrict__ dst) {
    int e = blockIdx.x * blockDim.x + threadIdx.x;
    if (e >= N_EDGES) return;
    int d = dst[e], s = src[e];
    int pos = atomicAdd(&g_off[d], 1);
    g_srcs[pos] = s;
    g_wsrc[pos] = g_dinv[s];
}

// ---------------- layer-1 input aggregation: XA = Â X  (5-wide) ----------------
__global__ __launch_bounds__(256) void k_agg_x(const float* __restrict__ x) {
    int i = blockIdx.x * blockDim.x + threadIdx.x;
    if (i >= N_NODES) return;
    float dv = g_dinv[i];
    float acc[5];
    #pragma unroll
    for (int k = 0; k < 5; k++) acc[k] = dv * x[(size_t)i * 5 + k];
    int cnt = g_cnt[i];
    int start = g_off[i] - cnt;
    for (int j = 0; j < cnt; j++) {
        int s = g_srcs[start + j];
        float w = g_wsrc[start + j];
        #pragma unroll
        for (int k = 0; k < 5; k++) acc[k] = fmaf(w, x[(size_t)s * 5 + k], acc[k]);
    }
    #pragma unroll
    for (int k = 0; k < 5; k++) g_XA[(size_t)i * 5 + k] = dv * acc[k];
}

// ---------------- layer-2 GEMM (fused layer-1 linear): A = relu(XA@W1+b1) @ W2 ----------------
#define WT_PITCH 130
#define L2_SMEM ((HID * WT_PITCH + 64 * HID + 5 * HID + HID) * 4)   // 102400 B
#define L3_SMEM ((HID * WT_PITCH + 64 * HID) * 4)                   //  99328 B

__global__ __launch_bounds__(256) void k_gemm_l2(const float* __restrict__ W1,
                                                 const float* __restrict__ b1,
                                                 const float* __restrict__ W2) {
    extern __shared__ float sh[];
    float* WsT = sh;                        // [128 cols][130 k]
    float* Is  = sh + HID * WT_PITCH;       // [64 rows][128 k]
    float* W1s = Is + 64 * HID;             // [5][128]
    float* b1s = W1s + 5 * HID;             // [128]
    int tid = threadIdx.x;

    const float4* W4 = (const float4*)W2;
    #pragma unroll
    for (int i = 0; i < 16; i++) {
        int idx4 = tid + 256 * i;
        int k = idx4 >> 5;
        int c0 = (idx4 & 31) * 4;
        float4 v = W4[idx4];
        WsT[(c0 + 0) * WT_PITCH + k] = v.x;
        WsT[(c0 + 1) * WT_PITCH + k] = v.y;
        WsT[(c0 + 2) * WT_PITCH + k] = v.z;
        WsT[(c0 + 3) * WT_PITCH + k] = v.w;
    }
    for (int i = tid; i < 5 * HID; i += 256) W1s[i] = W1[i];
    if (tid < HID) b1s[tid] = b1[tid];
    __syncthreads();

    int warp = tid >> 5, lane = tid & 31;
    int row0 = blockIdx.x * 64;

    // prologue: compute relu(XA@W1 + b1) for this warp's 8 rows
    {
        float4 w1v[5];
        #pragma unroll
        for (int k = 0; k < 5; k++) w1v[k] = ((const float4*)(W1s + k * HID))[lane];
        float4 b1v = ((const float4*)b1s)[lane];
        #pragma unroll
        for (int rr = 0; rr < 8; rr++) {
            int node = row0 + warp * 8 + rr;
            float4 h = make_float4(0.f, 0.f, 0.f, 0.f);
            if (node < N_NODES) {
                const float* xa = g_XA + (size_t)node * 5;
                float xk[5];
                #pragma unroll
                for (int k = 0; k < 5; k++) xk[k] = xa[k];
                h = b1v;
                #pragma unroll
                for (int k = 0; k < 5; k++) {
                    h.x = fmaf(xk[k], w1v[k].x, h.x);
                    h.y = fmaf(xk[k], w1v[k].y, h.y);
                    h.z = fmaf(xk[k], w1v[k].z, h.z);
                    h.w = fmaf(xk[k], w1v[k].w, h.w);
                }
                h.x = fmaxf(h.x, 0.f); h.y = fmaxf(h.y, 0.f);
                h.z = fmaxf(h.z, 0.f); h.w = fmaxf(h.w, 0.f);
            }
            ((float4*)(Is + (warp * 8 + rr) * HID))[lane] = h;
        }
    }
    __syncthreads();

    int r0 = warp * 8;
    u64 acc[8][4];
    #pragma unroll
    for (int rr = 0; rr < 8; rr++)
        #pragma unroll
        for (int cg = 0; cg < 4; cg++) acc[rr][cg] = 0ull;

    const float* isBase = Is + r0 * HID;
    #pragma unroll 4
    for (int kp = 0; kp < HID / 2; kp++) {
        u64 wv[4];
        #pragma unroll
        for (int cg = 0; cg < 4; cg++)
            wv[cg] = *(const u64*)&WsT[(lane + 32 * cg) * WT_PITCH + 2 * kp];
        #pragma unroll
        for (int rr = 0; rr < 8; rr++) {
            u64 xv = *(const u64*)&isBase[rr * HID + 2 * kp];
            #pragma unroll
            for (int cg = 0; cg < 4; cg++) FFMA2(acc[rr][cg], xv, wv[cg]);
        }
    }
    #pragma unroll
    for (int rr = 0; rr < 8; rr++) {
        int grow = row0 + r0 + rr;
        if (grow >= N_NODES) break;
        float* ap = g_A + (size_t)grow * HID;
        #pragma unroll
        for (int cg = 0; cg < 4; cg++) {
            F2U u; u.u = acc[rr][cg];
            ap[lane + 32 * cg] = u.f.x + u.f.y;
        }
    }
}

// ---------------- layer-3 GEMM (fused layer-2 aggregation): B = relu(Â·A + b2) @ W3 ----------------
__global__ __launch_bounds__(256) void k_gemm_l3(const float* __restrict__ b2,
                                                 const float* __restrict__ W3) {
    extern __shared__ float sh[];
    float* WsT = sh;                        // [128 cols][130 k]
    float* Is  = sh + HID * WT_PITCH;       // [64 rows][128 k]
    int tid = threadIdx.x;

    const float4* W4 = (const float4*)W3;
    #pragma unroll
    for (int i = 0; i < 16; i++) {
        int idx4 = tid + 256 * i;
        int k = idx4 >> 5;
        int c0 = (idx4 & 31) * 4;
        float4 v = W4[idx4];
        WsT[(c0 + 0) * WT_PITCH + k] = v.x;
        WsT[(c0 + 1) * WT_PITCH + k] = v.y;
        WsT[(c0 + 2) * WT_PITCH + k] = v.z;
        WsT[(c0 + 3) * WT_PITCH + k] = v.w;
    }

    int warp = tid >> 5, lane = tid & 31;
    int row0 = blockIdx.x * 64;
    const float4* __restrict__ A4 = (const float4*)g_A;
    float4 b2v = ((const float4*)b2)[lane];

    // prologue: gather-aggregate relu(dinv*(sum w*A[src] + dinv*A[node]) + b2) per row
    #pragma unroll 1
    for (int rr = 0; rr < 8; rr++) {
        int node = row0 + warp * 8 + rr;
        float4 h = make_float4(0.f, 0.f, 0.f, 0.f);
        if (node < N_NODES) {
            float dv = g_dinv[node];
            float4 a = A4[(size_t)node * 32 + lane];
            float4 acc;
            acc.x = dv * a.x; acc.y = dv * a.y; acc.z = dv * a.z; acc.w = dv * a.w;
            int cnt = g_cnt[node];
            int start = g_off[node] - cnt;
            for (int j0 = 0; j0 < cnt; j0 += 32) {
                int  rem = cnt - j0;
                bool ok  = lane < rem;
                int   sv = ok ? g_srcs[start + j0 + lane] : 0;
                float wv = ok ? g_wsrc[start + j0 + lane] : 0.f;
                int m = min(32, rem);
                #pragma unroll 4
                for (int j = 0; j < m; j++) {
                    int   sj = __shfl_sync(0xffffffffu, sv, j);
                    float wj = __shfl_sync(0xffffffffu, wv, j);
                    float4 v = A4[(size_t)sj * 32 + lane];
                    acc.x = fmaf(wj, v.x, acc.x);
                    acc.y = fmaf(wj, v.y, acc.y);
                    acc.z = fmaf(wj, v.z, acc.z);
                    acc.w = fmaf(wj, v.w, acc.w);
                }
            }
            h.x = fmaxf(fmaf(dv, acc.x, b2v.x), 0.f);
            h.y = fmaxf(fmaf(dv, acc.y, b2v.y), 0.f);
            h.z = fmaxf(fmaf(dv, acc.z, b2v.z), 0.f);
            h.w = fmaxf(fmaf(dv, acc.w, b2v.w), 0.f);
        }
        ((float4*)(Is + (warp * 8 + rr) * HID))[lane] = h;
    }
    __syncthreads();

    int r0 = warp * 8;
    u64 acc[8][4];
    #pragma unroll
    for (int rr = 0; rr < 8; rr++)
        #pragma unroll
        for (int cg = 0; cg < 4; cg++) acc[rr][cg] = 0ull;

    const float* isBase = Is + r0 * HID;
    #pragma unroll 4
    for (int kp = 0; kp < HID / 2; kp++) {
        u64 wv[4];
        #pragma unroll
        for (int cg = 0; cg < 4; cg++)
            wv[cg] = *(const u64*)&WsT[(lane + 32 * cg) * WT_PITCH + 2 * kp];
        #pragma unroll
        for (int rr = 0; rr < 8; rr++) {
            u64 xv = *(const u64*)&isBase[rr * HID + 2 * kp];
            #pragma unroll
            for (int cg = 0; cg < 4; cg++) FFMA2(acc[rr][cg], xv, wv[cg]);
        }
    }
    #pragma unroll
    for (int rr = 0; rr < 8; rr++) {
        int grow = row0 + r0 + rr;
        if (grow >= N_NODES) break;
        float* bp = g_B + (size_t)grow * HID;
        #pragma unroll
        for (int cg = 0; cg < 4; cg++) {
            F2U u; u.u = acc[rr][cg];
            bp[lane + 32 * cg] = u.f.x + u.f.y;
        }
    }
}

// ---------------- layer-3 aggregation fused with final FC ----------------
__global__ __launch_bounds__(256) void k_agg_final(const float* __restrict__ bias,
                                                   const float* __restrict__ Wfc,
                                                   const float* __restrict__ bfc,
                                                   float* __restrict__ out) {
    int g = blockIdx.x * blockDim.x + threadIdx.x;
    int node = g >> 5;
    int lane = g & 31;
    if (node >= N_NODES) return;

    const float4* __restrict__ B4 = (const float4*)g_B;
    float dv = g_dinv[node];
    float4 a = B4[(size_t)node * 32 + lane];
    float4 acc;
    acc.x = dv * a.x; acc.y = dv * a.y; acc.z = dv * a.z; acc.w = dv * a.w;

    int cnt = g_cnt[node];
    int start = g_off[node] - cnt;
    for (int j0 = 0; j0 < cnt; j0 += 32) {
        int  rem = cnt - j0;
        bool ok  = lane < rem;
        int   sv = ok ? g_srcs[start + j0 + lane] : 0;
        float wv = ok ? g_wsrc[start + j0 + lane] : 0.f;
        int m = min(32, rem);
        #pragma unroll 4
        for (int j = 0; j < m; j++) {
            int   sj = __shfl_sync(0xffffffffu, sv, j);
            float wj = __shfl_sync(0xffffffffu, wv, j);
            float4 v = B4[(size_t)sj * 32 + lane];
            acc.x = fmaf(wj, v.x, acc.x);
            acc.y = fmaf(wj, v.y, acc.y);
            acc.z = fmaf(wj, v.z, acc.z);
            acc.w = fmaf(wj, v.w, acc.w);
        }
    }
    float4 bb = ((const float4*)bias)[lane];
    float4 w  = ((const float4*)Wfc)[lane];
    float dot = fmaxf(fmaf(dv, acc.x, bb.x), 0.f) * w.x
              + fmaxf(fmaf(dv, acc.y, bb.y), 0.f) * w.y
              + fmaxf(fmaf(dv, acc.z, bb.z), 0.f) * w.z
              + fmaxf(fmaf(dv, acc.w, bb.w), 0.f) * w.w;
    #pragma unroll
    for (int o = 16; o > 0; o >>= 1) dot += __shfl_xor_sync(0xffffffffu, dot, o);
    if (lane == 0) out[node] = dot + bfc[0];
}

// ---------------- launcher ----------------
extern "C" void kernel_launch(void* const* d_in, const int* in_sizes, int n_in,
                              void* d_out, int out_size) {
    const float* x   = (const float*)d_in[0];
    const int*   ei  = (const int*)  d_in[1];
    const float* W1  = (const float*)d_in[2];
    const float* b1  = (const float*)d_in[3];
    const float* W2  = (const float*)d_in[4];
    const float* b2  = (const float*)d_in[5];
    const float* W3  = (const float*)d_in[6];
    const float* b3  = (const float*)d_in[7];
    const float* Wfc = (const float*)d_in[8];
    const float* bfc = (const float*)d_in[9];
    float* out = (float*)d_out;

    const int* src = ei;
    const int* dst = ei + N_EDGES;

    cudaFuncSetAttribute(k_gemm_l2, cudaFuncAttributeMaxDynamicSharedMemorySize, L2_SMEM);
    cudaFuncSetAttribute(k_gemm_l3, cudaFuncAttributeMaxDynamicSharedMemorySize, L3_SMEM);

    const int T = 256;
    int nb_nodes = (N_NODES + T - 1) / T;
    int nb_edges = (N_EDGES + T - 1) / T;
    int nb_warps = (N_NODES * 32 + T - 1) / T;
    int nb_gemm  = (N_NODES + 63) / 64;

    // CSR build
    k_zero     <<<nb_nodes, T>>>();
    k_deg_count<<<nb_edges, T>>>(dst);
    k_bsum     <<<NB_SCAN, SCAN_B>>>();
    k_bscan    <<<1, 128>>>();
    k_boff     <<<NB_SCAN, SCAN_B>>>();
    k_fill     <<<nb_edges, T>>>(src, dst);

    // pipeline
    k_agg_x   <<<nb_nodes, T>>>(x);
    k_gemm_l2 <<<nb_gemm, T, L2_SMEM>>>(W1, b1, W2);
    k_gemm_l3 <<<nb_gemm, T, L3_SMEM>>>(b2, W3);
    k_agg_final<<<nb_warps, T>>>(b3, Wfc, bfc, out);
}

// round 8
// speedup vs baseline: 1.1527x; 1.1527x over previous
#include <cuda_runtime.h>

#define N_NODES 100000
#define N_EDGES 1600000
#define HID 128
#define SCAN_B 1024
#define NB_SCAN ((N_NODES + SCAN_B - 1) / SCAN_B)   // 98

typedef unsigned long long u64;

// Scratch (no cudaMalloc allowed).
__device__ __align__(16) float g_A[(size_t)N_NODES * HID];   // layer GEMM output / message source
__device__ __align__(16) float g_B[(size_t)N_NODES * HID];   // aggregated features
__device__ __align__(16) float g_XA[(size_t)N_NODES * 5];    // aggregated raw input
__device__ __align__(16) float g_dinv[N_NODES];
__device__ int   g_cnt[N_NODES];
__device__ int   g_off[N_NODES];     // scan result; k_fill bumps it to segment END
__device__ int   g_bsum[NB_SCAN];
__device__ int   g_boff[NB_SCAN];
__device__ int   g_srcs[N_EDGES];
__device__ float g_wsrc[N_EDGES];

#define FFMA2(acc, a, b) asm("fma.rn.f32x2 %0, %1, %2, %0;" : "+l"(acc) : "l"(a), "l"(b))
union F2U { u64 u; float2 f; };

// ---------------- CSR build ----------------
__global__ void k_zero() {
    int i = blockIdx.x * blockDim.x + threadIdx.x;
    if (i < N_NODES) g_cnt[i] = 0;
}

__global__ void k_deg_count(const int* __restrict__ dst) {
    int e = blockIdx.x * blockDim.x + threadIdx.x;
    if (e < N_EDGES) atomicAdd(&g_cnt[dst[e]], 1);
}

// per-block sums of g_cnt + fused dinv computation
__global__ __launch_bounds__(SCAN_B) void k_bsum() {
    __shared__ int sh[SCAN_B];
    int t = threadIdx.x;
    int i = blockIdx.x * SCAN_B + t;
    int c = 0;
    if (i < N_NODES) {
        c = g_cnt[i];
        g_dinv[i] = rsqrtf((float)(c + 1));   // +1 self loop
    }
    sh[t] = c;
    __syncthreads();
    #pragma unroll
    for (int off = SCAN_B / 2; off > 0; off >>= 1) {
        if (t < off) sh[t] += sh[t + off];
        __syncthreads();
    }
    if (t == 0) g_bsum[blockIdx.x] = sh[0];
}

__global__ __launch_bounds__(128) void k_bscan() {
    __shared__ int sh[128];
    int t = threadIdx.x;
    sh[t] = (t < NB_SCAN) ? g_bsum[t] : 0;
    __syncthreads();
    #pragma unroll
    for (int off = 1; off < 128; off <<= 1) {
        int v = sh[t];
        int a = (t >= off) ? sh[t - off] : 0;
        __syncthreads();
        sh[t] = v + a;
        __syncthreads();
    }
    if (t < NB_SCAN) g_boff[t] = (t == 0) ? 0 : sh[t - 1];
}

__global__ __launch_bounds__(SCAN_B) void k_boff() {
    __shared__ int sh[SCAN_B];
    int t = threadIdx.x;
    int i = blockIdx.x * SCAN_B + t;
    int v = (i < N_NODES) ? g_cnt[i] : 0;
    sh[t] = v;
    __syncthreads();
    #pragma unroll
    for (int off = 1; off < SCAN_B; off <<= 1) {
        int cur = sh[t];
        int a = (t >= off) ? sh[t - off] : 0;
        __syncthreads();
        sh[t] = cur + a;
        __syncthreads();
    }
    if (i < N_NODES) g_off[i] = g_boff[blockIdx.x] + sh[t] - v;   // exclusive
}

// destructive fill: g_off[d] ends at segment END; start recovered as end - cnt
__global__ void k_fill(const int* __restrict__ src, const int* __restrict__ dst) {
    int e = blockIdx.x * blockDim.x + threadIdx.x;
    if (e >= N_EDGES) return;
    int d = dst[e], s = src[e];
    int pos = atomicAdd(&g_off[d], 1);
    g_srcs[pos] = s;
    g_wsrc[pos] = g_dinv[s];
}

// ---------------- layer-1 input aggregation: XA = Â X  (5-wide) ----------------
__global__ __launch_bounds__(256) void k_agg_x(const float* __restrict__ x) {
    int i = blockIdx.x * blockDim.x + threadIdx.x;
    if (i >= N_NODES) return;
    float dv = g_dinv[i];
    float acc[5];
    #pragma unroll
    for (int k = 0; k < 5; k++) acc[k] = dv * x[(size_t)i * 5 + k];
    int cnt = g_cnt[i];
    int start = g_off[i] - cnt;
    for (int j = 0; j < cnt; j++) {
        int s = g_srcs[start + j];
        float w = g_wsrc[start + j];
        #pragma unroll
        for (int k = 0; k < 5; k++) acc[k] = fmaf(w, x[(size_t)s * 5 + k], acc[k]);
    }
    #pragma unroll
    for (int k = 0; k < 5; k++) g_XA[(size_t)i * 5 + k] = dv * acc[k];
}

// ---------------- standalone aggregation: B = Â·A + bias  (warp per node) ----------------
__global__ __launch_bounds__(256) void k_agg(const float* __restrict__ bias) {
    int g = blockIdx.x * blockDim.x + threadIdx.x;
    int node = g >> 5;
    int lane = g & 31;
    if (node >= N_NODES) return;

    const float4* __restrict__ A4 = (const float4*)g_A;
    float dv = g_dinv[node];
    float4 a = A4[(size_t)node * 32 + lane];
    float4 acc;
    acc.x = dv * a.x; acc.y = dv * a.y; acc.z = dv * a.z; acc.w = dv * a.w;

    int cnt = g_cnt[node];
    int start = g_off[node] - cnt;
    for (int j0 = 0; j0 < cnt; j0 += 32) {
        int  rem = cnt - j0;
        bool ok  = lane < rem;
        int   sv = ok ? g_srcs[start + j0 + lane] : 0;
        float wv = ok ? g_wsrc[start + j0 + lane] : 0.f;
        int m = min(32, rem);
        #pragma unroll 4
        for (int j = 0; j < m; j++) {
            int   sj = __shfl_sync(0xffffffffu, sv, j);
            float wj = __shfl_sync(0xffffffffu, wv, j);
            float4 v = A4[(size_t)sj * 32 + lane];
            acc.x = fmaf(wj, v.x, acc.x);
            acc.y = fmaf(wj, v.y, acc.y);
            acc.z = fmaf(wj, v.z, acc.z);
            acc.w = fmaf(wj, v.w, acc.w);
        }
    }
    float4 bb = ((const float4*)bias)[lane];
    float4 o;
    o.x = fmaf(dv, acc.x, bb.x);
    o.y = fmaf(dv, acc.y, bb.y);
    o.z = fmaf(dv, acc.z, bb.z);
    o.w = fmaf(dv, acc.w, bb.w);
    ((float4*)g_B)[(size_t)node * 32 + lane] = o;
}

// ---------------- layer-2 GEMM (fused layer-1 linear): A = relu(XA@W1+b1) @ W2 ----------------
#define WT_PITCH 130
#define L2_SMEM ((HID * WT_PITCH + 64 * HID + 5 * HID + HID) * 4)   // 102400 B
#define L3_SMEM ((HID * WT_PITCH + 64 * HID) * 4)                   //  99328 B

__global__ __launch_bounds__(256) void k_gemm_l2(const float* __restrict__ W1,
                                                 const float* __restrict__ b1,
                                                 const float* __restrict__ W2) {
    extern __shared__ float sh[];
    float* WsT = sh;                        // [128 cols][130 k]
    float* Is  = sh + HID * WT_PITCH;       // [64 rows][128 k]
    float* W1s = Is + 64 * HID;             // [5][128]
    float* b1s = W1s + 5 * HID;             // [128]
    int tid = threadIdx.x;

    const float4* W4 = (const float4*)W2;
    #pragma unroll
    for (int i = 0; i < 16; i++) {
        int idx4 = tid + 256 * i;
        int k = idx4 >> 5;
        int c0 = (idx4 & 31) * 4;
        float4 v = W4[idx4];
        WsT[(c0 + 0) * WT_PITCH + k] = v.x;
        WsT[(c0 + 1) * WT_PITCH + k] = v.y;
        WsT[(c0 + 2) * WT_PITCH + k] = v.z;
        WsT[(c0 + 3) * WT_PITCH + k] = v.w;
    }
    for (int i = tid; i < 5 * HID; i += 256) W1s[i] = W1[i];
    if (tid < HID) b1s[tid] = b1[tid];
    __syncthreads();

    int warp = tid >> 5, lane = tid & 31;
    int row0 = blockIdx.x * 64;

    // prologue: relu(XA@W1 + b1) for this warp's 8 rows (register compute, no gather)
    {
        float4 w1v[5];
        #pragma unroll
        for (int k = 0; k < 5; k++) w1v[k] = ((const float4*)(W1s + k * HID))[lane];
        float4 b1v = ((const float4*)b1s)[lane];
        #pragma unroll
        for (int rr = 0; rr < 8; rr++) {
            int node = row0 + warp * 8 + rr;
            float4 h = make_float4(0.f, 0.f, 0.f, 0.f);
            if (node < N_NODES) {
                const float* xa = g_XA + (size_t)node * 5;
                float xk[5];
                #pragma unroll
                for (int k = 0; k < 5; k++) xk[k] = xa[k];
                h = b1v;
                #pragma unroll
                for (int k = 0; k < 5; k++) {
                    h.x = fmaf(xk[k], w1v[k].x, h.x);
                    h.y = fmaf(xk[k], w1v[k].y, h.y);
                    h.z = fmaf(xk[k], w1v[k].z, h.z);
                    h.w = fmaf(xk[k], w1v[k].w, h.w);
                }
                h.x = fmaxf(h.x, 0.f); h.y = fmaxf(h.y, 0.f);
                h.z = fmaxf(h.z, 0.f); h.w = fmaxf(h.w, 0.f);
            }
            ((float4*)(Is + (warp * 8 + rr) * HID))[lane] = h;
        }
    }
    __syncthreads();

    int r0 = warp * 8;
    u64 acc[8][4];
    #pragma unroll
    for (int rr = 0; rr < 8; rr++)
        #pragma unroll
        for (int cg = 0; cg < 4; cg++) acc[rr][cg] = 0ull;

    const float* isBase = Is + r0 * HID;
    #pragma unroll 4
    for (int kp = 0; kp < HID / 2; kp++) {
        u64 wv[4];
        #pragma unroll
        for (int cg = 0; cg < 4; cg++)
            wv[cg] = *(const u64*)&WsT[(lane + 32 * cg) * WT_PITCH + 2 * kp];
        #pragma unroll
        for (int rr = 0; rr < 8; rr++) {
            u64 xv = *(const u64*)&isBase[rr * HID + 2 * kp];
            #pragma unroll
            for (int cg = 0; cg < 4; cg++) FFMA2(acc[rr][cg], xv, wv[cg]);
        }
    }
    #pragma unroll
    for (int rr = 0; rr < 8; rr++) {
        int grow = row0 + r0 + rr;
        if (grow >= N_NODES) break;
        float* ap = g_A + (size_t)grow * HID;
        #pragma unroll
        for (int cg = 0; cg < 4; cg++) {
            F2U u; u.u = acc[rr][cg];
            ap[lane + 32 * cg] = u.f.x + u.f.y;
        }
    }
}

// ---------------- layer-3 GEMM: A = relu(B) @ W3  (plain, relu in tile load) ----------------
__global__ __launch_bounds__(256) void k_gemm_l3(const float* __restrict__ W3) {
    extern __shared__ float sh[];
    float* WsT = sh;                        // [128 cols][130 k]
    float* Is  = sh + HID * WT_PITCH;       // [64 rows][128 k]
    int tid = threadIdx.x;

    const float4* W4 = (const float4*)W3;
    #pragma unroll
    for (int i = 0; i < 16; i++) {
        int idx4 = tid + 256 * i;
        int k = idx4 >> 5;
        int c0 = (idx4 & 31) * 4;
        float4 v = W4[idx4];
        WsT[(c0 + 0) * WT_PITCH + k] = v.x;
        WsT[(c0 + 1) * WT_PITCH + k] = v.y;
        WsT[(c0 + 2) * WT_PITCH + k] = v.z;
        WsT[(c0 + 3) * WT_PITCH + k] = v.w;
    }

    int row0 = blockIdx.x * 64;
    float4* Is4 = (float4*)Is;
    #pragma unroll
    for (int i = 0; i < 8; i++) {
        int li = tid + 256 * i;
        int r = li >> 5, c = li & 31;
        int grow = row0 + r;
        float4 v = make_float4(0.f, 0.f, 0.f, 0.f);
        if (grow < N_NODES) v = ((const float4*)(g_B + (size_t)grow * HID))[c];
        v.x = fmaxf(v.x, 0.f); v.y = fmaxf(v.y, 0.f);
        v.z = fmaxf(v.z, 0.f); v.w = fmaxf(v.w, 0.f);
        Is4[li] = v;
    }
    __syncthreads();

    int warp = tid >> 5, lane = tid & 31;
    int r0 = warp * 8;
    u64 acc[8][4];
    #pragma unroll
    for (int rr = 0; rr < 8; rr++)
        #pragma unroll
        for (int cg = 0; cg < 4; cg++) acc[rr][cg] = 0ull;

    const float* isBase = Is + r0 * HID;
    #pragma unroll 4
    for (int kp = 0; kp < HID / 2; kp++) {
        u64 wv[4];
        #pragma unroll
        for (int cg = 0; cg < 4; cg++)
            wv[cg] = *(const u64*)&WsT[(lane + 32 * cg) * WT_PITCH + 2 * kp];
        #pragma unroll
        for (int rr = 0; rr < 8; rr++) {
            u64 xv = *(const u64*)&isBase[rr * HID + 2 * kp];
            #pragma unroll
            for (int cg = 0; cg < 4; cg++) FFMA2(acc[rr][cg], xv, wv[cg]);
        }
    }
    #pragma unroll
    for (int rr = 0; rr < 8; rr++) {
        int grow = row0 + r0 + rr;
        if (grow >= N_NODES) break;
        float* ap = g_A + (size_t)grow * HID;
        #pragma unroll
        for (int cg = 0; cg < 4; cg++) {
            F2U u; u.u = acc[rr][cg];
            ap[lane + 32 * cg] = u.f.x + u.f.y;
        }
    }
}

// ---------------- layer-3 aggregation fused with final FC ----------------
__global__ __launch_bounds__(256) void k_agg_final(const float* __restrict__ bias,
                                                   const float* __restrict__ Wfc,
                                                   const float* __restrict__ bfc,
                                                   float* __restrict__ out) {
    int g = blockIdx.x * blockDim.x + threadIdx.x;
    int node = g >> 5;
    int lane = g & 31;
    if (node >= N_NODES) return;

    const float4* __restrict__ A4 = (const float4*)g_A;
    float dv = g_dinv[node];
    float4 a = A4[(size_t)node * 32 + lane];
    float4 acc;
    acc.x = dv * a.x; acc.y = dv * a.y; acc.z = dv * a.z; acc.w = dv * a.w;

    int cnt = g_cnt[node];
    int start = g_off[node] - cnt;
    for (int j0 = 0; j0 < cnt; j0 += 32) {
        int  rem = cnt - j0;
        bool ok  = lane < rem;
        int   sv = ok ? g_srcs[start + j0 + lane] : 0;
        float wv = ok ? g_wsrc[start + j0 + lane] : 0.f;
        int m = min(32, rem);
        #pragma unroll 4
        for (int j = 0; j < m; j++) {
            int   sj = __shfl_sync(0xffffffffu, sv, j);
            float wj = __shfl_sync(0xffffffffu, wv, j);
            float4 v = A4[(size_t)sj * 32 + lane];
            acc.x = fmaf(wj, v.x, acc.x);
            acc.y = fmaf(wj, v.y, acc.y);
            acc.z = fmaf(wj, v.z, acc.z);
            acc.w = fmaf(wj, v.w, acc.w);
        }
    }
    float4 bb = ((const float4*)bias)[lane];
    float4 w  = ((const float4*)Wfc)[lane];
    float dot = fmaxf(fmaf(dv, acc.x, bb.x), 0.f) * w.x
              + fmaxf(fmaf(dv, acc.y, bb.y), 0.f) * w.y
              + fmaxf(fmaf(dv, acc.z, bb.z), 0.f) * w.z
              + fmaxf(fmaf(dv, acc.w, bb.w), 0.f) * w.w;
    #pragma unroll
    for (int o = 16; o > 0; o >>= 1) dot += __shfl_xor_sync(0xffffffffu, dot, o);
    if (lane == 0) out[node] = dot + bfc[0];
}

// ---------------- launcher ----------------
extern "C" void kernel_launch(void* const* d_in, const int* in_sizes, int n_in,
                              void* d_out, int out_size) {
    const float* x   = (const float*)d_in[0];
    const int*   ei  = (const int*)  d_in[1];
    const float* W1  = (const float*)d_in[2];
    const float* b1  = (const float*)d_in[3];
    const float* W2  = (const float*)d_in[4];
    const float* b2  = (const float*)d_in[5];
    const float* W3  = (const float*)d_in[6];
    const float* b3  = (const float*)d_in[7];
    const float* Wfc = (const float*)d_in[8];
    const float* bfc = (const float*)d_in[9];
    float* out = (float*)d_out;

    const int* src = ei;
    const int* dst = ei + N_EDGES;

    cudaFuncSetAttribute(k_gemm_l2, cudaFuncAttributeMaxDynamicSharedMemorySize, L2_SMEM);
    cudaFuncSetAttribute(k_gemm_l3, cudaFuncAttributeMaxDynamicSharedMemorySize, L3_SMEM);

    const int T = 256;
    int nb_nodes = (N_NODES + T - 1) / T;
    int nb_edges = (N_EDGES + T - 1) / T;
    int nb_warps = (N_NODES * 32 + T - 1) / T;
    int nb_gemm  = (N_NODES + 63) / 64;

    // CSR build
    k_zero     <<<nb_nodes, T>>>();
    k_deg_count<<<nb_edges, T>>>(dst);
    k_bsum     <<<NB_SCAN, SCAN_B>>>();
    k_bscan    <<<1, 128>>>();
    k_boff     <<<NB_SCAN, SCAN_B>>>();
    k_fill     <<<nb_edges, T>>>(src, dst);

    // pipeline
    k_agg_x   <<<nb_nodes, T>>>(x);
    k_gemm_l2 <<<nb_gemm, T, L2_SMEM>>>(W1, b1, W2);   // A = relu(XA@W1+b1) @ W2
    k_agg     <<<nb_warps, T>>>(b2);                    // B = Â·A + b2
    k_gemm_l3 <<<nb_gemm, T, L3_SMEM>>>(W3);            // A = relu(B) @ W3
    k_agg_final<<<nb_warps, T>>>(b3, Wfc, bfc, out);    // out = relu(Â·A+b3)·Wfc + bfc
}

// round 9
// speedup vs baseline: 1.2113x; 1.0509x over previous
#include <cuda_runtime.h>
#include <cuda_fp16.h>

#define N_NODES 100000
#define N_EDGES 1600000
#define HID 128
#define SCAN_B 1024
#define NB_SCAN ((N_NODES + SCAN_B - 1) / SCAN_B)   // 98

typedef unsigned long long u64;
typedef unsigned int u32;

// Scratch (no cudaMalloc allowed). Features stored fp16 (compute fp32).
__device__ __align__(16) __half g_Ah[(size_t)N_NODES * HID];  // GEMM outputs / message source
__device__ __align__(16) __half g_Bh[(size_t)N_NODES * HID];  // aggregated features
__device__ __align__(16) float  g_XA[(size_t)N_NODES * 5];    // aggregated raw input (fp32)
__device__ __align__(16) float  g_dinv[N_NODES];
__device__ int   g_cnt[N_NODES];
__device__ int   g_off[N_NODES];     // scan result; k_fill bumps it to segment END
__device__ int   g_bsum[NB_SCAN];
__device__ int   g_boff[NB_SCAN];
__device__ int   g_srcs[N_EDGES];
__device__ float g_wsrc[N_EDGES];

#define FFMA2(acc, a, b) asm("fma.rn.f32x2 %0, %1, %2, %0;" : "+l"(acc) : "l"(a), "l"(b))
union F2U { u64 u; float2 f; };

// ---------------- CSR build ----------------
__global__ void k_zero() {
    int i = blockIdx.x * blockDim.x + threadIdx.x;
    if (i < N_NODES) g_cnt[i] = 0;
}

__global__ void k_deg_count(const int* __restrict__ dst) {
    int e = blockIdx.x * blockDim.x + threadIdx.x;
    if (e < N_EDGES) atomicAdd(&g_cnt[dst[e]], 1);
}

__global__ __launch_bounds__(SCAN_B) void k_bsum() {
    __shared__ int sh[SCAN_B];
    int t = threadIdx.x;
    int i = blockIdx.x * SCAN_B + t;
    int c = 0;
    if (i < N_NODES) {
        c = g_cnt[i];
        g_dinv[i] = rsqrtf((float)(c + 1));   // +1 self loop
    }
    sh[t] = c;
    __syncthreads();
    #pragma unroll
    for (int off = SCAN_B / 2; off > 0; off >>= 1) {
        if (t < off) sh[t] += sh[t + off];
        __syncthreads();
    }
    if (t == 0) g_bsum[blockIdx.x] = sh[0];
}

__global__ __launch_bounds__(128) void k_bscan() {
    __shared__ int sh[128];
    int t = threadIdx.x;
    sh[t] = (t < NB_SCAN) ? g_bsum[t] : 0;
    __syncthreads();
    #pragma unroll
    for (int off = 1; off < 128; off <<= 1) {
        int v = sh[t];
        int a = (t >= off) ? sh[t - off] : 0;
        __syncthreads();
        sh[t] = v + a;
        __syncthreads();
    }
    if (t < NB_SCAN) g_boff[t] = (t == 0) ? 0 : sh[t - 1];
}

__global__ __launch_bounds__(SCAN_B) void k_boff() {
    __shared__ int sh[SCAN_B];
    int t = threadIdx.x;
    int i = blockIdx.x * SCAN_B + t;
    int v = (i < N_NODES) ? g_cnt[i] : 0;
    sh[t] = v;
    __syncthreads();
    #pragma unroll
    for (int off = 1; off < SCAN_B; off <<= 1) {
        int cur = sh[t];
        int a = (t >= off) ? sh[t - off] : 0;
        __syncthreads();
        sh[t] = cur + a;
        __syncthreads();
    }
    if (i < N_NODES) g_off[i] = g_boff[blockIdx.x] + sh[t] - v;   // exclusive
}

// destructive fill: g_off[d] ends at segment END; start recovered as end - cnt
__global__ void k_fill(const int* __restrict__ src, const int* __restrict__ dst) {
    int e = blockIdx.x * blockDim.x + threadIdx.x;
    if (e >= N_EDGES) return;
    int d = dst[e], s = src[e];
    int pos = atomicAdd(&g_off[d], 1);
    g_srcs[pos] = s;
    g_wsrc[pos] = g_dinv[s];
}

// ---------------- layer-1 input aggregation: XA = Â X  (5-wide, fp32) ----------------
__global__ __launch_bounds__(256) void k_agg_x(const float* __restrict__ x) {
    int i = blockIdx.x * blockDim.x + threadIdx.x;
    if (i >= N_NODES) return;
    float dv = g_dinv[i];
    float acc[5];
    #pragma unroll
    for (int k = 0; k < 5; k++) acc[k] = dv * x[(size_t)i * 5 + k];
    int cnt = g_cnt[i];
    int start = g_off[i] - cnt;
    for (int j = 0; j < cnt; j++) {
        int s = g_srcs[start + j];
        float w = g_wsrc[start + j];
        #pragma unroll
        for (int k = 0; k < 5; k++) acc[k] = fmaf(w, x[(size_t)s * 5 + k], acc[k]);
    }
    #pragma unroll
    for (int k = 0; k < 5; k++) g_XA[(size_t)i * 5 + k] = dv * acc[k];
}

// ---------------- aggregation: Bh = Â·Ah + bias  (warp/node; fp16 in/out, fp32 math) ----------------
__global__ __launch_bounds__(256) void k_agg(const float* __restrict__ bias) {
    int g = blockIdx.x * blockDim.x + threadIdx.x;
    int node = g >> 5;
    int lane = g & 31;
    if (node >= N_NODES) return;

    const uint2* __restrict__ A2 = (const uint2*)g_Ah;   // 4 halves per uint2; 32 uint2 per row
    float dv = g_dinv[node];
    uint2 raw = A2[(size_t)node * 32 + lane];
    float2 s0 = __half22float2(*(const half2*)&raw.x);
    float2 s1 = __half22float2(*(const half2*)&raw.y);
    float4 acc;
    acc.x = dv * s0.x; acc.y = dv * s0.y; acc.z = dv * s1.x; acc.w = dv * s1.y;

    int cnt = g_cnt[node];
    int start = g_off[node] - cnt;
    for (int j0 = 0; j0 < cnt; j0 += 32) {
        int  rem = cnt - j0;
        bool ok  = lane < rem;
        int   sv = ok ? g_srcs[start + j0 + lane] : 0;
        float wv = ok ? g_wsrc[start + j0 + lane] : 0.f;
        int m = min(32, rem);
        #pragma unroll 4
        for (int j = 0; j < m; j++) {
            int   sj = __shfl_sync(0xffffffffu, sv, j);
            float wj = __shfl_sync(0xffffffffu, wv, j);
            uint2 r = A2[(size_t)sj * 32 + lane];
            float2 f0 = __half22float2(*(const half2*)&r.x);
            float2 f1 = __half22float2(*(const half2*)&r.y);
            acc.x = fmaf(wj, f0.x, acc.x);
            acc.y = fmaf(wj, f0.y, acc.y);
            acc.z = fmaf(wj, f1.x, acc.z);
            acc.w = fmaf(wj, f1.y, acc.w);
        }
    }
    float4 bb = ((const float4*)bias)[lane];
    float2 o0, o1;
    o0.x = fmaf(dv, acc.x, bb.x);
    o0.y = fmaf(dv, acc.y, bb.y);
    o1.x = fmaf(dv, acc.z, bb.z);
    o1.y = fmaf(dv, acc.w, bb.w);
    half2 p0 = __float22half2_rn(o0);
    half2 p1 = __float22half2_rn(o1);
    uint2 w;
    w.x = *(const u32*)&p0;
    w.y = *(const u32*)&p1;
    ((uint2*)g_Bh)[(size_t)node * 32 + lane] = w;
}

// ---------------- layer-2 GEMM (fused layer-1 linear): Ah = relu(XA@W1+b1) @ W2 ----------------
#define WT_PITCH 130
#define L2_SMEM ((HID * WT_PITCH + 64 * HID + 5 * HID + HID) * 4)   // 102400 B
#define L3_SMEM ((HID * WT_PITCH + 64 * HID) * 4)                   //  99328 B

__global__ __launch_bounds__(256) void k_gemm_l2(const float* __restrict__ W1,
                                                 const float* __restrict__ b1,
                                                 const float* __restrict__ W2) {
    extern __shared__ float sh[];
    float* WsT = sh;                        // [128 cols][130 k]
    float* Is  = sh + HID * WT_PITCH;       // [64 rows][128 k]
    float* W1s = Is + 64 * HID;             // [5][128]
    float* b1s = W1s + 5 * HID;             // [128]
    int tid = threadIdx.x;

    const float4* W4 = (const float4*)W2;
    #pragma unroll
    for (int i = 0; i < 16; i++) {
        int idx4 = tid + 256 * i;
        int k = idx4 >> 5;
        int c0 = (idx4 & 31) * 4;
        float4 v = W4[idx4];
        WsT[(c0 + 0) * WT_PITCH + k] = v.x;
        WsT[(c0 + 1) * WT_PITCH + k] = v.y;
        WsT[(c0 + 2) * WT_PITCH + k] = v.z;
        WsT[(c0 + 3) * WT_PITCH + k] = v.w;
    }
    for (int i = tid; i < 5 * HID; i += 256) W1s[i] = W1[i];
    if (tid < HID) b1s[tid] = b1[tid];
    __syncthreads();

    int warp = tid >> 5, lane = tid & 31;
    int row0 = blockIdx.x * 64;

    // prologue: relu(XA@W1 + b1) for this warp's 8 rows (register compute, no gather)
    {
        float4 w1v[5];
        #pragma unroll
        for (int k = 0; k < 5; k++) w1v[k] = ((const float4*)(W1s + k * HID))[lane];
        float4 b1v = ((const float4*)b1s)[lane];
        #pragma unroll
        for (int rr = 0; rr < 8; rr++) {
            int node = row0 + warp * 8 + rr;
            float4 h = make_float4(0.f, 0.f, 0.f, 0.f);
            if (node < N_NODES) {
                const float* xa = g_XA + (size_t)node * 5;
                float xk[5];
                #pragma unroll
                for (int k = 0; k < 5; k++) xk[k] = xa[k];
                h = b1v;
                #pragma unroll
                for (int k = 0; k < 5; k++) {
                    h.x = fmaf(xk[k], w1v[k].x, h.x);
                    h.y = fmaf(xk[k], w1v[k].y, h.y);
                    h.z = fmaf(xk[k], w1v[k].z, h.z);
                    h.w = fmaf(xk[k], w1v[k].w, h.w);
                }
                h.x = fmaxf(h.x, 0.f); h.y = fmaxf(h.y, 0.f);
                h.z = fmaxf(h.z, 0.f); h.w = fmaxf(h.w, 0.f);
            }
            ((float4*)(Is + (warp * 8 + rr) * HID))[lane] = h;
        }
    }
    __syncthreads();

    int r0 = warp * 8;
    u64 acc[8][4];
    #pragma unroll
    for (int rr = 0; rr < 8; rr++)
        #pragma unroll
        for (int cg = 0; cg < 4; cg++) acc[rr][cg] = 0ull;

    const float* isBase = Is + r0 * HID;
    #pragma unroll 4
    for (int kp = 0; kp < HID / 2; kp++) {
        u64 wv[4];
        #pragma unroll
        for (int cg = 0; cg < 4; cg++)
            wv[cg] = *(const u64*)&WsT[(lane + 32 * cg) * WT_PITCH + 2 * kp];
        #pragma unroll
        for (int rr = 0; rr < 8; rr++) {
            u64 xv = *(const u64*)&isBase[rr * HID + 2 * kp];
            #pragma unroll
            for (int cg = 0; cg < 4; cg++) FFMA2(acc[rr][cg], xv, wv[cg]);
        }
    }
    #pragma unroll
    for (int rr = 0; rr < 8; rr++) {
        int grow = row0 + r0 + rr;
        if (grow >= N_NODES) break;
        __half* ap = g_Ah + (size_t)grow * HID;
        #pragma unroll
        for (int cg = 0; cg < 4; cg++) {
            F2U u; u.u = acc[rr][cg];
            ap[lane + 32 * cg] = __float2half_rn(u.f.x + u.f.y);
        }
    }
}

// ---------------- layer-3 GEMM: Ah = relu(Bh) @ W3  (fp16 in/out, fp32 math) ----------------
__global__ __launch_bounds__(256) void k_gemm_l3(const float* __restrict__ W3) {
    extern __shared__ float sh[];
    float* WsT = sh;                        // [128 cols][130 k]
    float* Is  = sh + HID * WT_PITCH;       // [64 rows][128 k]
    int tid = threadIdx.x;

    const float4* W4 = (const float4*)W3;
    #pragma unroll
    for (int i = 0; i < 16; i++) {
        int idx4 = tid + 256 * i;
        int k = idx4 >> 5;
        int c0 = (idx4 & 31) * 4;
        float4 v = W4[idx4];
        WsT[(c0 + 0) * WT_PITCH + k] = v.x;
        WsT[(c0 + 1) * WT_PITCH + k] = v.y;
        WsT[(c0 + 2) * WT_PITCH + k] = v.z;
        WsT[(c0 + 3) * WT_PITCH + k] = v.w;
    }

    int row0 = blockIdx.x * 64;
    const uint2* __restrict__ B2 = (const uint2*)g_Bh;   // 32 uint2 (=128 halves) per row
    #pragma unroll
    for (int i = 0; i < 8; i++) {
        int li = tid + 256 * i;                // 0..2047 (one uint2 = 4 cols each)
        int r = li >> 5, c = li & 31;
        int grow = row0 + r;
        float4 v = make_float4(0.f, 0.f, 0.f, 0.f);
        if (grow < N_NODES) {
            uint2 raw = B2[(size_t)grow * 32 + c];
            float2 f0 = __half22float2(*(const half2*)&raw.x);
            float2 f1 = __half22float2(*(const half2*)&raw.y);
            v.x = fmaxf(f0.x, 0.f); v.y = fmaxf(f0.y, 0.f);
            v.z = fmaxf(f1.x, 0.f); v.w = fmaxf(f1.y, 0.f);
        }
        ((float4*)Is)[li] = v;
    }
    __syncthreads();

    int warp = tid >> 5, lane = tid & 31;
    int r0 = warp * 8;
    u64 acc[8][4];
    #pragma unroll
    for (int rr = 0; rr < 8; rr++)
        #pragma unroll
        for (int cg = 0; cg < 4; cg++) acc[rr][cg] = 0ull;

    const float* isBase = Is + r0 * HID;
    #pragma unroll 4
    for (int kp = 0; kp < HID / 2; kp++) {
        u64 wv[4];
        #pragma unroll
        for (int cg = 0; cg < 4; cg++)
            wv[cg] = *(const u64*)&WsT[(lane + 32 * cg) * WT_PITCH + 2 * kp];
        #pragma unroll
        for (int rr = 0; rr < 8; rr++) {
            u64 xv = *(const u64*)&isBase[rr * HID + 2 * kp];
            #pragma unroll
            for (int cg = 0; cg < 4; cg++) FFMA2(acc[rr][cg], xv, wv[cg]);
        }
    }
    #pragma unroll
    for (int rr = 0; rr < 8; rr++) {
        int grow = row0 + r0 + rr;
        if (grow >= N_NODES) break;
        __half* ap = g_Ah + (size_t)grow * HID;
        #pragma unroll
        for (int cg = 0; cg < 4; cg++) {
            F2U u; u.u = acc[rr][cg];
            ap[lane + 32 * cg] = __float2half_rn(u.f.x + u.f.y);
        }
    }
}

// ---------------- layer-3 aggregation fused with final FC (fp16 gather, fp32 math) ----------------
__global__ __launch_bounds__(256) void k_agg_final(const float* __restrict__ bias,
                                                   const float* __restrict__ Wfc,
                                                   const float* __restrict__ bfc,
                                                   float* __restrict__ out) {
    int g = blockIdx.x * blockDim.x + threadIdx.x;
    int node = g >> 5;
    int lane = g & 31;
    if (node >= N_NODES) return;

    const uint2* __restrict__ A2 = (const uint2*)g_Ah;
    float dv = g_dinv[node];
    uint2 raw = A2[(size_t)node * 32 + lane];
    float2 s0 = __half22float2(*(const half2*)&raw.x);
    float2 s1 = __half22float2(*(const half2*)&raw.y);
    float4 acc;
    acc.x = dv * s0.x; acc.y = dv * s0.y; acc.z = dv * s1.x; acc.w = dv * s1.y;

    int cnt = g_cnt[node];
    int start = g_off[node] - cnt;
    for (int j0 = 0; j0 < cnt; j0 += 32) {
        int  rem = cnt - j0;
        bool ok  = lane < rem;
        int   sv = ok ? g_srcs[start + j0 + lane] : 0;
        float wv = ok ? g_wsrc[start + j0 + lane] : 0.f;
        int m = min(32, rem);
        #pragma unroll 4
        for (int j = 0; j < m; j++) {
            int   sj = __shfl_sync(0xffffffffu, sv, j);
            float wj = __shfl_sync(0xffffffffu, wv, j);
            uint2 r = A2[(size_t)sj * 32 + lane];
            float2 f0 = __half22float2(*(const half2*)&r.x);
            float2 f1 = __half22float2(*(const half2*)&r.y);
            acc.x = fmaf(wj, f0.x, acc.x);
            acc.y = fmaf(wj, f0.y, acc.y);
            acc.z = fmaf(wj, f1.x, acc.z);
            acc.w = fmaf(wj, f1.y, acc.w);
        }
    }
    float4 bb = ((const float4*)bias)[lane];
    float4 w  = ((const float4*)Wfc)[lane];
    float dot = fmaxf(fmaf(dv, acc.x, bb.x), 0.f) * w.x
              + fmaxf(fmaf(dv, acc.y, bb.y), 0.f) * w.y
              + fmaxf(fmaf(dv, acc.z, bb.z), 0.f) * w.z
              + fmaxf(fmaf(dv, acc.w, bb.w), 0.f) * w.w;
    #pragma unroll
    for (int o = 16; o > 0; o >>= 1) dot += __shfl_xor_sync(0xffffffffu, dot, o);
    if (lane == 0) out[node] = dot + bfc[0];
}

// ---------------- launcher ----------------
extern "C" void kernel_launch(void* const* d_in, const int* in_sizes, int n_in,
                              void* d_out, int out_size) {
    const float* x   = (const float*)d_in[0];
    const int*   ei  = (const int*)  d_in[1];
    const float* W1  = (const float*)d_in[2];
    const float* b1  = (const float*)d_in[3];
    const float* W2  = (const float*)d_in[4];
    const float* b2  = (const float*)d_in[5];
    const float* W3  = (const float*)d_in[6];
    const float* b3  = (const float*)d_in[7];
    const float* Wfc = (const float*)d_in[8];
    const float* bfc = (const float*)d_in[9];
    float* out = (float*)d_out;

    const int* src = ei;
    const int* dst = ei + N_EDGES;

    cudaFuncSetAttribute(k_gemm_l2, cudaFuncAttributeMaxDynamicSharedMemorySize, L2_SMEM);
    cudaFuncSetAttribute(k_gemm_l3, cudaFuncAttributeMaxDynamicSharedMemorySize, L3_SMEM);

    const int T = 256;
    int nb_nodes = (N_NODES + T - 1) / T;
    int nb_edges = (N_EDGES + T - 1) / T;
    int nb_warps = (N_NODES * 32 + T - 1) / T;
    int nb_gemm  = (N_NODES + 63) / 64;

    // CSR build
    k_zero     <<<nb_nodes, T>>>();
    k_deg_count<<<nb_edges, T>>>(dst);
    k_bsum     <<<NB_SCAN, SCAN_B>>>();
    k_bscan    <<<1, 128>>>();
    k_boff     <<<NB_SCAN, SCAN_B>>>();
    k_fill     <<<nb_edges, T>>>(src, dst);

    // pipeline
    k_agg_x   <<<nb_nodes, T>>>(x);
    k_gemm_l2 <<<nb_gemm, T, L2_SMEM>>>(W1, b1, W2);   // Ah = relu(XA@W1+b1) @ W2
    k_agg     <<<nb_warps, T>>>(b2);                    // Bh = Â·Ah + b2
    k_gemm_l3 <<<nb_gemm, T, L3_SMEM>>>(W3);            // Ah = relu(Bh) @ W3
    k_agg_final<<<nb_warps, T>>>(b3, Wfc, bfc, out);    // out = relu(Â·Ah+b3)·Wfc + bfc
}

// round 11
// speedup vs baseline: 1.6248x; 1.3413x over previous
#include <cuda_runtime.h>
#include <cuda_fp16.h>
#include <mma.h>
using namespace nvcuda;

#define N_NODES 100000
#define N_EDGES 1600000
#define HID 128
#define SCAN_B 1024
#define NB_SCAN ((N_NODES + SCAN_B - 1) / SCAN_B)   // 98

typedef unsigned long long u64;
typedef unsigned int u32;

// Scratch (no cudaMalloc allowed). Features stored fp16 (aggregation math fp32).
__device__ __align__(16) __half g_Ah[(size_t)N_NODES * HID];  // GEMM outputs / message source
__device__ __align__(16) __half g_Bh[(size_t)N_NODES * HID];  // aggregated features
__device__ __align__(16) float  g_XA[(size_t)N_NODES * 5];    // aggregated raw input (fp32)
__device__ __align__(16) float  g_dinv[N_NODES];
__device__ int   g_cnt[N_NODES];
__device__ int   g_off[N_NODES];     // scan result; k_fill bumps it to segment END
__device__ int   g_bsum[NB_SCAN];
__device__ int   g_boff[NB_SCAN];
__device__ int   g_srcs[N_EDGES];
__device__ float g_wsrc[N_EDGES];

// ---------------- CSR build ----------------
__global__ void k_zero() {
    int i = blockIdx.x * blockDim.x + threadIdx.x;
    if (i < N_NODES) g_cnt[i] = 0;
}

__global__ void k_deg_count(const int* __restrict__ dst) {
    int e = blockIdx.x * blockDim.x + threadIdx.x;
    if (e < N_EDGES) atomicAdd(&g_cnt[dst[e]], 1);
}

__global__ __launch_bounds__(SCAN_B) void k_bsum() {
    __shared__ int sh[SCAN_B];
    int t = threadIdx.x;
    int i = blockIdx.x * SCAN_B + t;
    int c = 0;
    if (i < N_NODES) {
        c = g_cnt[i];
        g_dinv[i] = rsqrtf((float)(c + 1));   // +1 self loop
    }
    sh[t] = c;
    __syncthreads();
    #pragma unroll
    for (int off = SCAN_B / 2; off > 0; off >>= 1) {
        if (t < off) sh[t] += sh[t + off];
        __syncthreads();
    }
    if (t == 0) g_bsum[blockIdx.x] = sh[0];
}

__global__ __launch_bounds__(128) void k_bscan() {
    __shared__ int sh[128];
    int t = threadIdx.x;
    sh[t] = (t < NB_SCAN) ? g_bsum[t] : 0;
    __syncthreads();
    #pragma unroll
    for (int off = 1; off < 128; off <<= 1) {
        int v = sh[t];
        int a = (t >= off) ? sh[t - off] : 0;
        __syncthreads();
        sh[t] = v + a;
        __syncthreads();
    }
    if (t < NB_SCAN) g_boff[t] = (t == 0) ? 0 : sh[t - 1];
}

__global__ __launch_bounds__(SCAN_B) void k_boff() {
    __shared__ int sh[SCAN_B];
    int t = threadIdx.x;
    int i = blockIdx.x * SCAN_B + t;
    int v = (i < N_NODES) ? g_cnt[i] : 0;
    sh[t] = v;
    __syncthreads();
    #pragma unroll
    for (int off = 1; off < SCAN_B; off <<= 1) {
        int cur = sh[t];
        int a = (t >= off) ? sh[t - off] : 0;
        __syncthreads();
        sh[t] = cur + a;
        __syncthreads();
    }
    if (i < N_NODES) g_off[i] = g_boff[blockIdx.x] + sh[t] - v;   // exclusive
}

// destructive fill: g_off[d] ends at segment END; start recovered as end - cnt
__global__ void k_fill(const int* __restrict__ src, const int* __restrict__ dst) {
    int e = blockIdx.x * blockDim.x + threadIdx.x;
    if (e >= N_EDGES) return;
    int d = dst[e], s = src[e];
    int pos = atomicAdd(&g_off[d], 1);
    g_srcs[pos] = s;
    g_wsrc[pos] = g_dinv[s];
}

// ---------------- layer-1 input aggregation: XA = Â X  (5-wide, fp32) ----------------
__global__ __launch_bounds__(256) void k_agg_x(const float* __restrict__ x) {
    int i = blockIdx.x * blockDim.x + threadIdx.x;
    if (i >= N_NODES) return;
    float dv = g_dinv[i];
    float acc[5];
    #pragma unroll
    for (int k = 0; k < 5; k++) acc[k] = dv * x[(size_t)i * 5 + k];
    int cnt = g_cnt[i];
    int start = g_off[i] - cnt;
    for (int j = 0; j < cnt; j++) {
        int s = g_srcs[start + j];
        float w = g_wsrc[start + j];
        #pragma unroll
        for (int k = 0; k < 5; k++) acc[k] = fmaf(w, x[(size_t)s * 5 + k], acc[k]);
    }
    #pragma unroll
    for (int k = 0; k < 5; k++) g_XA[(size_t)i * 5 + k] = dv * acc[k];
}

// ---------------- aggregation: Bh = Â·Ah + bias  (warp/node; fp16 in/out, fp32 math) ----------------
__global__ __launch_bounds__(256) void k_agg(const float* __restrict__ bias) {
    int g = blockIdx.x * blockDim.x + threadIdx.x;
    int node = g >> 5;
    int lane = g & 31;
    if (node >= N_NODES) return;

    const uint2* __restrict__ A2 = (const uint2*)g_Ah;   // 4 halves per uint2; 32 uint2 per row
    float dv = g_dinv[node];
    uint2 raw = A2[(size_t)node * 32 + lane];
    float2 s0 = __half22float2(*(const half2*)&raw.x);
    float2 s1 = __half22float2(*(const half2*)&raw.y);
    float4 acc;
    acc.x = dv * s0.x; acc.y = dv * s0.y; acc.z = dv * s1.x; acc.w = dv * s1.y;

    int cnt = g_cnt[node];
    int start = g_off[node] - cnt;
    for (int j0 = 0; j0 < cnt; j0 += 32) {
        int  rem = cnt - j0;
        bool ok  = lane < rem;
        int   sv = ok ? g_srcs[start + j0 + lane] : 0;
        float wv = ok ? g_wsrc[start + j0 + lane] : 0.f;
        int m = min(32, rem);
        #pragma unroll 4
        for (int j = 0; j < m; j++) {
            int   sj = __shfl_sync(0xffffffffu, sv, j);
            float wj = __shfl_sync(0xffffffffu, wv, j);
            uint2 r = A2[(size_t)sj * 32 + lane];
            float2 f0 = __half22float2(*(const half2*)&r.x);
            float2 f1 = __half22float2(*(const half2*)&r.y);
            acc.x = fmaf(wj, f0.x, acc.x);
            acc.y = fmaf(wj, f0.y, acc.y);
            acc.z = fmaf(wj, f1.x, acc.z);
            acc.w = fmaf(wj, f1.y, acc.w);
        }
    }
    float4 bb = ((const float4*)bias)[lane];
    float2 o0, o1;
    o0.x = fmaf(dv, acc.x, bb.x);
    o0.y = fmaf(dv, acc.y, bb.y);
    o1.x = fmaf(dv, acc.z, bb.z);
    o1.y = fmaf(dv, acc.w, bb.w);
    half2 p0 = __float22half2_rn(o0);
    half2 p1 = __float22half2_rn(o1);
    uint2 w;
    w.x = *(const u32*)&p0;
    w.y = *(const u32*)&p1;
    ((uint2*)g_Bh)[(size_t)node * 32 + lane] = w;
}

// ---------------- tensor-core GEMM layout constants ----------------
#define A_PITCH 136              // halves (272 B rows)
#define W_PITCH 136
#define SC_PITCH 132             // floats
#define WH_BYTES (HID * W_PITCH * 2)          // 34816 (one W plane)
#define AT_BYTES (64 * A_PITCH * 2)           // 17408
#define L2_SMEM (2 * WH_BYTES + AT_BYTES + (5 * HID + HID) * 4)  // 90112 B
#define L3_SMEM (2 * WH_BYTES + AT_BYTES)                        // 87040 B

// split a float into hi/lo halves: w = hi + lo with |lo| <~ w*2^-12
__device__ __forceinline__ void split_h(float v, __half& hi, __half& lo) {
    hi = __float2half_rn(v);
    lo = __float2half_rn(v - __half2float(hi));
}

// ---------------- layer-2 GEMM (fused layer-1 linear): Ah = relu(XA@W1+b1) @ W2 ----------------
__global__ __launch_bounds__(256) void k_gemm_l2(const float* __restrict__ W1,
                                                 const float* __restrict__ b1,
                                                 const float* __restrict__ W2) {
    extern __shared__ char shc[];
    __half* Wh  = (__half*)shc;                       // [128][136] W2 hi
    __half* Wl  = Wh + HID * W_PITCH;                 // [128][136] W2 lo
    __half* At  = Wl + HID * W_PITCH;                 // [64][136] input tile
    float*  W1s = (float*)(At + 64 * A_PITCH);        // [5][128]
    float*  b1s = W1s + 5 * HID;                      // [128]
    int tid = threadIdx.x;

    // W2 fp32 -> split fp16 hi/lo
    const float4* W4 = (const float4*)W2;
    #pragma unroll
    for (int i = 0; i < 16; i++) {
        int idx4 = tid + 256 * i;                     // 0..4095
        int k = idx4 >> 5, c0 = (idx4 & 31) * 4;
        float4 v = W4[idx4];
        __half h0, l0, h1, l1, h2, l2, h3, l3;
        split_h(v.x, h0, l0); split_h(v.y, h1, l1);
        split_h(v.z, h2, l2); split_h(v.w, h3, l3);
        __half* wp = Wh + k * W_PITCH + c0;
        wp[0] = h0; wp[1] = h1; wp[2] = h2; wp[3] = h3;
        __half* lp = Wl + k * W_PITCH + c0;
        lp[0] = l0; lp[1] = l1; lp[2] = l2; lp[3] = l3;
    }
    for (int i = tid; i < 5 * HID; i += 256) W1s[i] = W1[i];
    if (tid < HID) b1s[tid] = b1[tid];
    __syncthreads();

    int warp = tid >> 5, lane = tid & 31;
    int row0 = blockIdx.x * 64;

    // prologue: relu(XA@W1 + b1) -> At (fp32 math, fp16 store)
    {
        float4 w1v[5];
        #pragma unroll
        for (int k = 0; k < 5; k++) w1v[k] = ((const float4*)(W1s + k * HID))[lane];
        float4 b1v = ((const float4*)b1s)[lane];
        #pragma unroll
        for (int rr = 0; rr < 8; rr++) {
            int node = row0 + warp * 8 + rr;
            float4 h = make_float4(0.f, 0.f, 0.f, 0.f);
            if (node < N_NODES) {
                const float* xa = g_XA + (size_t)node * 5;
                float xk[5];
                #pragma unroll
                for (int k = 0; k < 5; k++) xk[k] = xa[k];
                h = b1v;
                #pragma unroll
                for (int k = 0; k < 5; k++) {
                    h.x = fmaf(xk[k], w1v[k].x, h.x);
                    h.y = fmaf(xk[k], w1v[k].y, h.y);
                    h.z = fmaf(xk[k], w1v[k].z, h.z);
                    h.w = fmaf(xk[k], w1v[k].w, h.w);
                }
                h.x = fmaxf(h.x, 0.f); h.y = fmaxf(h.y, 0.f);
                h.z = fmaxf(h.z, 0.f); h.w = fmaxf(h.w, 0.f);
            }
            __half* dp = At + (warp * 8 + rr) * A_PITCH + lane * 4;
            *(half2*)dp       = __floats2half2_rn(h.x, h.y);
            *(half2*)(dp + 2) = __floats2half2_rn(h.z, h.w);
        }
    }
    __syncthreads();

    // mainloop: warp tile 16 rows x 64 cols, split-W double HMMA
    int rt = warp >> 1, ct = warp & 1;
    wmma::fragment<wmma::accumulator, 16, 16, 16, float> fc[4];
    #pragma unroll
    for (int j = 0; j < 4; j++) wmma::fill_fragment(fc[j], 0.0f);
    #pragma unroll
    for (int k0 = 0; k0 < 8; k0++) {
        wmma::fragment<wmma::matrix_a, 16, 16, 16, __half, wmma::row_major> fa;
        wmma::load_matrix_sync(fa, At + rt * 16 * A_PITCH + k0 * 16, A_PITCH);
        #pragma unroll
        for (int j = 0; j < 4; j++) {
            wmma::fragment<wmma::matrix_b, 16, 16, 16, __half, wmma::row_major> fb;
            wmma::load_matrix_sync(fb, Wh + k0 * 16 * W_PITCH + ct * 64 + j * 16, W_PITCH);
            wmma::mma_sync(fc[j], fa, fb, fc[j]);
            wmma::load_matrix_sync(fb, Wl + k0 * 16 * W_PITCH + ct * 64 + j * 16, W_PITCH);
            wmma::mma_sync(fc[j], fa, fb, fc[j]);
        }
    }
    __syncthreads();                          // done reading W planes; reuse hi as scratch
    float* sc = (float*)Wh;                   // [64][132] floats (33792 B <= 34816 B)
    #pragma unroll
    for (int j = 0; j < 4; j++)
        wmma::store_matrix_sync(sc + rt * 16 * SC_PITCH + ct * 64 + j * 16, fc[j],
                                SC_PITCH, wmma::mem_row_major);
    __syncthreads();

    // convert scratch -> g_Ah (fp16)
    #pragma unroll
    for (int i = 0; i < 16; i++) {
        int li = tid + 256 * i;               // 0..4095 = 64 rows x 64 col-pairs
        int r = li >> 6, c2 = (li & 63) * 2;
        int grow = row0 + r;
        if (grow < N_NODES) {
            float2 v = *(float2*)&sc[r * SC_PITCH + c2];
            *(half2*)&g_Ah[(size_t)grow * HID + c2] = __floats2half2_rn(v.x, v.y);
        }
    }
}

// ---------------- layer-3 GEMM: Ah = relu(Bh) @ W3  (split-W HMMA) ----------------
__global__ __launch_bounds__(256) void k_gemm_l3(const float* __restrict__ W3) {
    extern __shared__ char shc[];
    __half* Wh = (__half*)shc;                        // [128][136] hi
    __half* Wl = Wh + HID * W_PITCH;                  // [128][136] lo
    __half* At = Wl + HID * W_PITCH;                  // [64][136]
    int tid = threadIdx.x;

    const float4* W4 = (const float4*)W3;
    #pragma unroll
    for (int i = 0; i < 16; i++) {
        int idx4 = tid + 256 * i;
        int k = idx4 >> 5, c0 = (idx4 & 31) * 4;
        float4 v = W4[idx4];
        __half h0, l0, h1, l1, h2, l2, h3, l3;
        split_h(v.x, h0, l0); split_h(v.y, h1, l1);
        split_h(v.z, h2, l2); split_h(v.w, h3, l3);
        __half* wp = Wh + k * W_PITCH + c0;
        wp[0] = h0; wp[1] = h1; wp[2] = h2; wp[3] = h3;
        __half* lp = Wl + k * W_PITCH + c0;
        lp[0] = l0; lp[1] = l1; lp[2] = l2; lp[3] = l3;
    }

    int row0 = blockIdx.x * 64;
    // tile load: relu(Bh) -> At (pure fp16, relu exact)
    half2 z2 = __floats2half2_rn(0.f, 0.f);
    #pragma unroll
    for (int i = 0; i < 16; i++) {
        int li = tid + 256 * i;               // 64 rows x 64 half2
        int r = li >> 6, c2 = (li & 63) * 2;
        int grow = row0 + r;
        half2 v = z2;
        if (grow < N_NODES) v = *(const half2*)&g_Bh[(size_t)grow * HID + c2];
        *(half2*)&At[r * A_PITCH + c2] = __hmax2(v, z2);
    }
    __syncthreads();

    int warp = tid >> 5;
    int rt = warp >> 1, ct = warp & 1;
    wmma::fragment<wmma::accumulator, 16, 16, 16, float> fc[4];
    #pragma unroll
    for (int j = 0; j < 4; j++) wmma::fill_fragment(fc[j], 0.0f);
    #pragma unroll
    for (int k0 = 0; k0 < 8; k0++) {
        wmma::fragment<wmma::matrix_a, 16, 16, 16, __half, wmma::row_major> fa;
        wmma::load_matrix_sync(fa, At + rt * 16 * A_PITCH + k0 * 16, A_PITCH);
        #pragma unroll
        for (int j = 0; j < 4; j++) {
            wmma::fragment<wmma::matrix_b, 16, 16, 16, __half, wmma::row_major> fb;
            wmma::load_matrix_sync(fb, Wh + k0 * 16 * W_PITCH + ct * 64 + j * 16, W_PITCH);
            wmma::mma_sync(fc[j], fa, fb, fc[j]);
            wmma::load_matrix_sync(fb, Wl + k0 * 16 * W_PITCH + ct * 64 + j * 16, W_PITCH);
            wmma::mma_sync(fc[j], fa, fb, fc[j]);
        }
    }
    __syncthreads();
    float* sc = (float*)Wh;
    #pragma unroll
    for (int j = 0; j < 4; j++)
        wmma::store_matrix_sync(sc + rt * 16 * SC_PITCH + ct * 64 + j * 16, fc[j],
                                SC_PITCH, wmma::mem_row_major);
    __syncthreads();

    #pragma unroll
    for (int i = 0; i < 16; i++) {
        int li = tid + 256 * i;
        int r = li >> 6, c2 = (li & 63) * 2;
        int grow = row0 + r;
        if (grow < N_NODES) {
            float2 v = *(float2*)&sc[r * SC_PITCH + c2];
            *(half2*)&g_Ah[(size_t)grow * HID + c2] = __floats2half2_rn(v.x, v.y);
        }
    }
}

// ---------------- layer-3 aggregation fused with final FC (fp16 gather, fp32 math) ----------------
__global__ __launch_bounds__(256) void k_agg_final(const float* __restrict__ bias,
                                                   const float* __restrict__ Wfc,
                                                   const float* __restrict__ bfc,
                                                   float* __restrict__ out) {
    int g = blockIdx.x * blockDim.x + threadIdx.x;
    int node = g >> 5;
    int lane = g & 31;
    if (node >= N_NODES) return;

    const uint2* __restrict__ A2 = (const uint2*)g_Ah;
    float dv = g_dinv[node];
    uint2 raw = A2[(size_t)node * 32 + lane];
    float2 s0 = __half22float2(*(const half2*)&raw.x);
    float2 s1 = __half22float2(*(const half2*)&raw.y);
    float4 acc;
    acc.x = dv * s0.x; acc.y = dv * s0.y; acc.z = dv * s1.x; acc.w = dv * s1.y;

    int cnt = g_cnt[node];
    int start = g_off[node] - cnt;
    for (int j0 = 0; j0 < cnt; j0 += 32) {
        int  rem = cnt - j0;
        bool ok  = lane < rem;
        int   sv = ok ? g_srcs[start + j0 + lane] : 0;
        float wv = ok ? g_wsrc[start + j0 + lane] : 0.f;
        int m = min(32, rem);
        #pragma unroll 4
        for (int j = 0; j < m; j++) {
            int   sj = __shfl_sync(0xffffffffu, sv, j);
            float wj = __shfl_sync(0xffffffffu, wv, j);
            uint2 r = A2[(size_t)sj * 32 + lane];
            float2 f0 = __half22float2(*(const half2*)&r.x);
            float2 f1 = __half22float2(*(const half2*)&r.y);
            acc.x = fmaf(wj, f0.x, acc.x);
            acc.y = fmaf(wj, f0.y, acc.y);
            acc.z = fmaf(wj, f1.x, acc.z);
            acc.w = fmaf(wj, f1.y, acc.w);
        }
    }
    float4 bb = ((const float4*)bias)[lane];
    float4 w  = ((const float4*)Wfc)[lane];
    float dot = fmaxf(fmaf(dv, acc.x, bb.x), 0.f) * w.x
              + fmaxf(fmaf(dv, acc.y, bb.y), 0.f) * w.y
              + fmaxf(fmaf(dv, acc.z, bb.z), 0.f) * w.z
              + fmaxf(fmaf(dv, acc.w, bb.w), 0.f) * w.w;
    #pragma unroll
    for (int o = 16; o > 0; o >>= 1) dot += __shfl_xor_sync(0xffffffffu, dot, o);
    if (lane == 0) out[node] = dot + bfc[0];
}

// ---------------- launcher ----------------
extern "C" void kernel_launch(void* const* d_in, const int* in_sizes, int n_in,
                              void* d_out, int out_size) {
    const float* x   = (const float*)d_in[0];
    const int*   ei  = (const int*)  d_in[1];
    const float* W1  = (const float*)d_in[2];
    const float* b1  = (const float*)d_in[3];
    const float* W2  = (const float*)d_in[4];
    const float* b2  = (const float*)d_in[5];
    const float* W3  = (const float*)d_in[6];
    const float* b3  = (const float*)d_in[7];
    const float* Wfc = (const float*)d_in[8];
    const float* bfc = (const float*)d_in[9];
    float* out = (float*)d_out;

    const int* src = ei;
    const int* dst = ei + N_EDGES;

    cudaFuncSetAttribute(k_gemm_l2, cudaFuncAttributeMaxDynamicSharedMemorySize, L2_SMEM);
    cudaFuncSetAttribute(k_gemm_l3, cudaFuncAttributeMaxDynamicSharedMemorySize, L3_SMEM);

    const int T = 256;
    int nb_nodes = (N_NODES + T - 1) / T;
    int nb_edges = (N_EDGES + T - 1) / T;
    int nb_warps = (N_NODES * 32 + T - 1) / T;
    int nb_gemm  = (N_NODES + 63) / 64;

    // CSR build
    k_zero     <<<nb_nodes, T>>>();
    k_deg_count<<<nb_edges, T>>>(dst);
    k_bsum     <<<NB_SCAN, SCAN_B>>>();
    k_bscan    <<<1, 128>>>();
    k_boff     <<<NB_SCAN, SCAN_B>>>();
    k_fill     <<<nb_edges, T>>>(src, dst);

    // pipeline
    k_agg_x   <<<nb_nodes, T>>>(x);
    k_gemm_l2 <<<nb_gemm, T, L2_SMEM>>>(W1, b1, W2);   // Ah = relu(XA@W1+b1) @ W2  (split-W HMMA)
    k_agg     <<<nb_warps, T>>>(b2);                    // Bh = Â·Ah + b2
    k_gemm_l3 <<<nb_gemm, T, L3_SMEM>>>(W3);            // Ah = relu(Bh) @ W3        (split-W HMMA)
    k_agg_final<<<nb_warps, T>>>(b3, Wfc, bfc, out);    // out = relu(Â·Ah+b3)·Wfc + bfc
}

// round 12
// speedup vs baseline: 1.7554x; 1.0804x over previous
#include <cuda_runtime.h>
#include <cuda_fp16.h>
#include <mma.h>
using namespace nvcuda;

#define N_NODES 100000
#define N_EDGES 1600000
#define HID 128
#define SCAN_B 1024
#define NB_SCAN ((N_NODES + SCAN_B - 1) / SCAN_B)   // 98

typedef unsigned long long u64;
typedef unsigned int u32;

// Scratch (no cudaMalloc allowed). Features stored fp16 (aggregation math fp32).
__device__ __align__(16) __half g_Ah[(size_t)N_NODES * HID];  // GEMM outputs / message source
__device__ __align__(16) __half g_Bh[(size_t)N_NODES * HID];  // aggregated features
__device__ __align__(16) float  g_XA[(size_t)N_NODES * 5];    // aggregated raw input (fp32)
__device__ __align__(16) float  g_dinv[N_NODES];
__device__ int   g_cnt[N_NODES];
__device__ int   g_off[N_NODES];     // scan result; k_fill bumps it to segment END
__device__ int   g_bsum[NB_SCAN];
__device__ __align__(8) uint2 g_edge[N_EDGES];   // (src, dinv[src] bits) interleaved

// ---------------- CSR build ----------------
__global__ void k_zero() {
    int i = blockIdx.x * blockDim.x + threadIdx.x;
    if (i < N_NODES) g_cnt[i] = 0;
}

__global__ void k_deg_count(const int* __restrict__ dst) {
    int e = blockIdx.x * blockDim.x + threadIdx.x;
    if (e < N_EDGES) atomicAdd(&g_cnt[dst[e]], 1);
}

// per-block sums of g_cnt + fused dinv computation
__global__ __launch_bounds__(SCAN_B) void k_bsum() {
    __shared__ int sh[SCAN_B];
    int t = threadIdx.x;
    int i = blockIdx.x * SCAN_B + t;
    int c = 0;
    if (i < N_NODES) {
        c = g_cnt[i];
        g_dinv[i] = rsqrtf((float)(c + 1));   // +1 self loop
    }
    sh[t] = c;
    __syncthreads();
    #pragma unroll
    for (int off = SCAN_B / 2; off > 0; off >>= 1) {
        if (t < off) sh[t] += sh[t + off];
        __syncthreads();
    }
    if (t == 0) g_bsum[blockIdx.x] = sh[0];
}

// in-block exclusive scan + inline prefix of block sums (merged bscan)
__global__ __launch_bounds__(SCAN_B) void k_boff() {
    __shared__ int sh[SCAN_B];
    __shared__ int base;
    int t = threadIdx.x;
    if (t < 32) {
        int s = 0;
        for (int i = t; i < (int)blockIdx.x; i += 32) s += g_bsum[i];
        #pragma unroll
        for (int o = 16; o > 0; o >>= 1) s += __shfl_xor_sync(0xffffffffu, s, o);
        if (t == 0) base = s;
    }
    int i = blockIdx.x * SCAN_B + t;
    int v = (i < N_NODES) ? g_cnt[i] : 0;
    sh[t] = v;
    __syncthreads();
    #pragma unroll
    for (int off = 1; off < SCAN_B; off <<= 1) {
        int cur = sh[t];
        int a = (t >= off) ? sh[t - off] : 0;
        __syncthreads();
        sh[t] = cur + a;
        __syncthreads();
    }
    if (i < N_NODES) g_off[i] = base + sh[t] - v;   // exclusive
}

// destructive fill: g_off[d] ends at segment END; start recovered as end - cnt
// single 8-byte interleaved store per edge
__global__ void k_fill(const int* __restrict__ src, const int* __restrict__ dst) {
    int e = blockIdx.x * blockDim.x + threadIdx.x;
    if (e >= N_EDGES) return;
    int d = dst[e], s = src[e];
    int pos = atomicAdd(&g_off[d], 1);
    uint2 ev;
    ev.x = (u32)s;
    ev.y = __float_as_uint(g_dinv[s]);
    g_edge[pos] = ev;
}

// ---------------- layer-1 input aggregation: XA = Â X  (5-wide, fp32) ----------------
__global__ __launch_bounds__(256) void k_agg_x(const float* __restrict__ x) {
    int i = blockIdx.x * blockDim.x + threadIdx.x;
    if (i >= N_NODES) return;
    float dv = g_dinv[i];
    float acc[5];
    #pragma unroll
    for (int k = 0; k < 5; k++) acc[k] = dv * x[(size_t)i * 5 + k];
    int cnt = g_cnt[i];
    int start = g_off[i] - cnt;
    for (int j = 0; j < cnt; j++) {
        uint2 ev = g_edge[start + j];
        int s = (int)ev.x;
        float w = __uint_as_float(ev.y);
        #pragma unroll
        for (int k = 0; k < 5; k++) acc[k] = fmaf(w, x[(size_t)s * 5 + k], acc[k]);
    }
    #pragma unroll
    for (int k = 0; k < 5; k++) g_XA[(size_t)i * 5 + k] = dv * acc[k];
}

// ---------------- aggregation: Bh = Â·Ah + bias  (warp/node; fp16 in/out, fp32 math) ----------------
__global__ __launch_bounds__(256) void k_agg(const float* __restrict__ bias) {
    int g = blockIdx.x * blockDim.x + threadIdx.x;
    int node = g >> 5;
    int lane = g & 31;
    if (node >= N_NODES) return;

    const uint2* __restrict__ A2 = (const uint2*)g_Ah;   // 4 halves per uint2; 32 uint2 per row
    float dv = g_dinv[node];
    uint2 raw = A2[(size_t)node * 32 + lane];
    float2 s0 = __half22float2(*(const half2*)&raw.x);
    float2 s1 = __half22float2(*(const half2*)&raw.y);
    float4 acc;
    acc.x = dv * s0.x; acc.y = dv * s0.y; acc.z = dv * s1.x; acc.w = dv * s1.y;

    int cnt = g_cnt[node];
    int start = g_off[node] - cnt;
    for (int j0 = 0; j0 < cnt; j0 += 32) {
        int  rem = cnt - j0;
        bool ok  = lane < rem;
        uint2 ev = ok ? g_edge[start + j0 + lane] : make_uint2(0u, 0u);
        int m = min(32, rem);
        #pragma unroll 4
        for (int j = 0; j < m; j++) {
            int   sj = (int)__shfl_sync(0xffffffffu, ev.x, j);
            float wj = __uint_as_float(__shfl_sync(0xffffffffu, ev.y, j));
            uint2 r = A2[(size_t)sj * 32 + lane];
            float2 f0 = __half22float2(*(const half2*)&r.x);
            float2 f1 = __half22float2(*(const half2*)&r.y);
            acc.x = fmaf(wj, f0.x, acc.x);
            acc.y = fmaf(wj, f0.y, acc.y);
            acc.z = fmaf(wj, f1.x, acc.z);
            acc.w = fmaf(wj, f1.y, acc.w);
        }
    }
    float4 bb = ((const float4*)bias)[lane];
    float2 o0, o1;
    o0.x = fmaf(dv, acc.x, bb.x);
    o0.y = fmaf(dv, acc.y, bb.y);
    o1.x = fmaf(dv, acc.z, bb.z);
    o1.y = fmaf(dv, acc.w, bb.w);
    half2 p0 = __float22half2_rn(o0);
    half2 p1 = __float22half2_rn(o1);
    uint2 w;
    w.x = *(const u32*)&p0;
    w.y = *(const u32*)&p1;
    ((uint2*)g_Bh)[(size_t)node * 32 + lane] = w;
}

// ---------------- tensor-core GEMM layout constants (128-row CTA tiles) ----------------
#define TILE_ROWS 128
#define A_PITCH 136              // halves (272 B rows)
#define W_PITCH 136
#define SC_PITCH 132             // floats
#define WH_BYTES (HID * W_PITCH * 2)            // 34816 (one W plane)
#define AT_BYTES (TILE_ROWS * A_PITCH * 2)      // 34816
#define L2_SMEM (2 * WH_BYTES + AT_BYTES + (5 * HID + HID) * 4)  // 107008 B
#define L3_SMEM (2 * WH_BYTES + AT_BYTES)                        // 104448 B

// split a float into hi/lo halves: w = hi + lo with |lo| <~ w*2^-12
__device__ __forceinline__ void split_h(float v, __half& hi, __half& lo) {
    hi = __float2half_rn(v);
    lo = __float2half_rn(v - __half2float(hi));
}

__device__ __forceinline__ void load_split_W(__half* Wh, __half* Wl,
                                             const float* __restrict__ W, int tid) {
    const float4* W4 = (const float4*)W;
    #pragma unroll
    for (int i = 0; i < 16; i++) {
        int idx4 = tid + 256 * i;                     // 0..4095
        int k = idx4 >> 5, c0 = (idx4 & 31) * 4;
        float4 v = W4[idx4];
        __half h0, l0, h1, l1, h2, l2, h3, l3;
        split_h(v.x, h0, l0); split_h(v.y, h1, l1);
        split_h(v.z, h2, l2); split_h(v.w, h3, l3);
        __half* wp = Wh + k * W_PITCH + c0;
        wp[0] = h0; wp[1] = h1; wp[2] = h2; wp[3] = h3;
        __half* lp = Wl + k * W_PITCH + c0;
        lp[0] = l0; lp[1] = l1; lp[2] = l2; lp[3] = l3;
    }
}

// shared mainloop + epilogue: warp 'warp' computes rows [warp*16, warp*16+16) x 128 cols
__device__ __forceinline__ void mma_tile_and_store(const __half* Wh, const __half* Wl,
                                                   const __half* At, float* sc,
                                                   __half* gout, int row0, int tid) {
    int warp = tid >> 5;
    wmma::fragment<wmma::accumulator, 16, 16, 16, float> fc[8];
    #pragma unroll
    for (int j = 0; j < 8; j++) wmma::fill_fragment(fc[j], 0.0f);
    #pragma unroll
    for (int k0 = 0; k0 < 8; k0++) {
        wmma::fragment<wmma::matrix_a, 16, 16, 16, __half, wmma::row_major> fa;
        wmma::load_matrix_sync(fa, At + warp * 16 * A_PITCH + k0 * 16, A_PITCH);
        #pragma unroll
        for (int j = 0; j < 8; j++) {
            wmma::fragment<wmma::matrix_b, 16, 16, 16, __half, wmma::row_major> fb;
            wmma::load_matrix_sync(fb, Wh + k0 * 16 * W_PITCH + j * 16, W_PITCH);
            wmma::mma_sync(fc[j], fa, fb, fc[j]);
            wmma::load_matrix_sync(fb, Wl + k0 * 16 * W_PITCH + j * 16, W_PITCH);
            wmma::mma_sync(fc[j], fa, fb, fc[j]);
        }
    }
    __syncthreads();                          // done reading W planes; reuse as fp32 scratch
    #pragma unroll
    for (int j = 0; j < 8; j++)
        wmma::store_matrix_sync(sc + warp * 16 * SC_PITCH + j * 16, fc[j],
                                SC_PITCH, wmma::mem_row_major);
    __syncthreads();
    // convert scratch -> gout (fp16): 128 rows x 64 half2
    #pragma unroll
    for (int i = 0; i < 32; i++) {
        int li = tid + 256 * i;               // 0..8191
        int r = li >> 6, c2 = (li & 63) * 2;
        int grow = row0 + r;
        if (grow < N_NODES) {
            float2 v = *(float2*)&sc[r * SC_PITCH + c2];
            *(half2*)&gout[(size_t)grow * HID + c2] = __floats2half2_rn(v.x, v.y);
        }
    }
}

// ---------------- layer-2 GEMM (fused layer-1 linear): Ah = relu(XA@W1+b1) @ W2 ----------------
__global__ __launch_bounds__(256) void k_gemm_l2(const float* __restrict__ W1,
                                                 const float* __restrict__ b1,
                                                 const float* __restrict__ W2) {
    extern __shared__ char shc[];
    __half* Wh  = (__half*)shc;                       // [128][136] W2 hi
    __half* Wl  = Wh + HID * W_PITCH;                 // [128][136] W2 lo
    __half* At  = Wl + HID * W_PITCH;                 // [128][136] input tile
    float*  W1s = (float*)(At + TILE_ROWS * A_PITCH); // [5][128]
    float*  b1s = W1s + 5 * HID;                      // [128]
    int tid = threadIdx.x;

    load_split_W(Wh, Wl, W2, tid);
    for (int i = tid; i < 5 * HID; i += 256) W1s[i] = W1[i];
    if (tid < HID) b1s[tid] = b1[tid];
    __syncthreads();

    int warp = tid >> 5, lane = tid & 31;
    int row0 = blockIdx.x * TILE_ROWS;

    // prologue: relu(XA@W1 + b1) -> At (fp32 math, fp16 store); warp handles 16 rows
    {
        float4 w1v[5];
        #pragma unroll
        for (int k = 0; k < 5; k++) w1v[k] = ((const float4*)(W1s + k * HID))[lane];
        float4 b1v = ((const float4*)b1s)[lane];
        #pragma unroll
        for (int rr = 0; rr < 16; rr++) {
            int node = row0 + warp * 16 + rr;
            float4 h = make_float4(0.f, 0.f, 0.f, 0.f);
            if (node < N_NODES) {
                const float* xa = g_XA + (size_t)node * 5;
                float xk[5];
                #pragma unroll
                for (int k = 0; k < 5; k++) xk[k] = xa[k];
                h = b1v;
                #pragma unroll
                for (int k = 0; k < 5; k++) {
                    h.x = fmaf(xk[k], w1v[k].x, h.x);
                    h.y = fmaf(xk[k], w1v[k].y, h.y);
                    h.z = fmaf(xk[k], w1v[k].z, h.z);
                    h.w = fmaf(xk[k], w1v[k].w, h.w);
                }
                h.x = fmaxf(h.x, 0.f); h.y = fmaxf(h.y, 0.f);
                h.z = fmaxf(h.z, 0.f); h.w = fmaxf(h.w, 0.f);
            }
            __half* dp = At + (warp * 16 + rr) * A_PITCH + lane * 4;
            *(half2*)dp       = __floats2half2_rn(h.x, h.y);
            *(half2*)(dp + 2) = __floats2half2_rn(h.z, h.w);
        }
    }
    __syncthreads();

    mma_tile_and_store(Wh, Wl, At, (float*)Wh, g_Ah, row0, tid);
}

// ---------------- layer-3 GEMM: Ah = relu(Bh) @ W3  (split-W HMMA) ----------------
__global__ __launch_bounds__(256) void k_gemm_l3(const float* __restrict__ W3) {
    extern __shared__ char shc[];
    __half* Wh = (__half*)shc;                        // [128][136] hi
    __half* Wl = Wh + HID * W_PITCH;                  // [128][136] lo
    __half* At = Wl + HID * W_PITCH;                  // [128][136]
    int tid = threadIdx.x;

    load_split_W(Wh, Wl, W3, tid);

    int row0 = blockIdx.x * TILE_ROWS;
    // tile load: relu(Bh) -> At (pure fp16, relu exact): 128 rows x 64 half2
    half2 z2 = __floats2half2_rn(0.f, 0.f);
    #pragma unroll
    for (int i = 0; i < 32; i++) {
        int li = tid + 256 * i;
        int r = li >> 6, c2 = (li & 63) * 2;
        int grow = row0 + r;
        half2 v = z2;
        if (grow < N_NODES) v = *(const half2*)&g_Bh[(size_t)grow * HID + c2];
        *(half2*)&At[r * A_PITCH + c2] = __hmax2(v, z2);
    }
    __syncthreads();

    mma_tile_and_store(Wh, Wl, At, (float*)Wh, g_Ah, row0, tid);
}

// ---------------- layer-3 aggregation fused with final FC (fp16 gather, fp32 math) ----------------
__global__ __launch_bounds__(256) void k_agg_final(const float* __restrict__ bias,
                                                   const float* __restrict__ Wfc,
                                                   const float* __restrict__ bfc,
                                                   float* __restrict__ out) {
    int g = blockIdx.x * blockDim.x + threadIdx.x;
    int node = g >> 5;
    int lane = g & 31;
    if (node >= N_NODES) return;

    const uint2* __restrict__ A2 = (const uint2*)g_Ah;
    float dv = g_dinv[node];
    uint2 raw = A2[(size_t)node * 32 + lane];
    float2 s0 = __half22float2(*(const half2*)&raw.x);
    float2 s1 = __half22float2(*(const half2*)&raw.y);
    float4 acc;
    acc.x = dv * s0.x; acc.y = dv * s0.y; acc.z = dv * s1.x; acc.w = dv * s1.y;

    int cnt = g_cnt[node];
    int start = g_off[node] - cnt;
    for (int j0 = 0; j0 < cnt; j0 += 32) {
        int  rem = cnt - j0;
        bool ok  = lane < rem;
        uint2 ev = ok ? g_edge[start + j0 + lane] : make_uint2(0u, 0u);
        int m = min(32, rem);
        #pragma unroll 4
        for (int j = 0; j < m; j++) {
            int   sj = (int)__shfl_sync(0xffffffffu, ev.x, j);
            float wj = __uint_as_float(__shfl_sync(0xffffffffu, ev.y, j));
            uint2 r = A2[(size_t)sj * 32 + lane];
            float2 f0 = __half22float2(*(const half2*)&r.x);
            float2 f1 = __half22float2(*(const half2*)&r.y);
            acc.x = fmaf(wj, f0.x, acc.x);
            acc.y = fmaf(wj, f0.y, acc.y);
            acc.z = fmaf(wj, f1.x, acc.z);
            acc.w = fmaf(wj, f1.y, acc.w);
        }
    }
    float4 bb = ((const float4*)bias)[lane];
    float4 w  = ((const float4*)Wfc)[lane];
    float dot = fmaxf(fmaf(dv, acc.x, bb.x), 0.f) * w.x
              + fmaxf(fmaf(dv, acc.y, bb.y), 0.f) * w.y
              + fmaxf(fmaf(dv, acc.z, bb.z), 0.f) * w.z
              + fmaxf(fmaf(dv, acc.w, bb.w), 0.f) * w.w;
    #pragma unroll
    for (int o = 16; o > 0; o >>= 1) dot += __shfl_xor_sync(0xffffffffu, dot, o);
    if (lane == 0) out[node] = dot + bfc[0];
}

// ---------------- launcher ----------------
extern "C" void kernel_launch(void* const* d_in, const int* in_sizes, int n_in,
                              void* d_out, int out_size) {
    const float* x   = (const float*)d_in[0];
    const int*   ei  = (const int*)  d_in[1];
    const float* W1  = (const float*)d_in[2];
    const float* b1  = (const float*)d_in[3];
    const float* W2  = (const float*)d_in[4];
    const float* b2  = (const float*)d_in[5];
    const float* W3  = (const float*)d_in[6];
    const float* b3  = (const float*)d_in[7];
    const float* Wfc = (const float*)d_in[8];
    const float* bfc = (const float*)d_in[9];
    float* out = (float*)d_out;

    const int* src = ei;
    const int* dst = ei + N_EDGES;

    cudaFuncSetAttribute(k_gemm_l2, cudaFuncAttributeMaxDynamicSharedMemorySize, L2_SMEM);
    cudaFuncSetAttribute(k_gemm_l3, cudaFuncAttributeMaxDynamicSharedMemorySize, L3_SMEM);

    const int T = 256;
    int nb_nodes = (N_NODES + T - 1) / T;
    int nb_edges = (N_EDGES + T - 1) / T;
    int nb_warps = (N_NODES * 32 + T - 1) / T;
    int nb_gemm  = (N_NODES + TILE_ROWS - 1) / TILE_ROWS;

    // CSR build
    k_zero     <<<nb_nodes, T>>>();
    k_deg_count<<<nb_edges, T>>>(dst);
    k_bsum     <<<NB_SCAN, SCAN_B>>>();
    k_boff     <<<NB_SCAN, SCAN_B>>>();
    k_fill     <<<nb_edges, T>>>(src, dst);

    // pipeline
    k_agg_x   <<<nb_nodes, T>>>(x);
    k_gemm_l2 <<<nb_gemm, T, L2_SMEM>>>(W1, b1, W2);   // Ah = relu(XA@W1+b1) @ W2  (split-W HMMA)
    k_agg     <<<nb_warps, T>>>(b2);                    // Bh = Â·Ah + b2
    k_gemm_l3 <<<nb_gemm, T, L3_SMEM>>>(W3);            // Ah = relu(Bh) @ W3        (split-W HMMA)
    k_agg_final<<<nb_warps, T>>>(b3, Wfc, bfc, out);    // out = relu(Â·Ah+b3)·Wfc + bfc
}

// round 13
// speedup vs baseline: 1.8426x; 1.0497x over previous
#include <cuda_runtime.h>
#include <cuda_fp16.h>
#include <mma.h>
using namespace nvcuda;

#define N_NODES 100000
#define N_EDGES 1600000
#define HID 128
#define SCAN_B 1024
#define NB_SCAN ((N_NODES + SCAN_B - 1) / SCAN_B)   // 98

typedef unsigned long long u64;
typedef unsigned int u32;

// Scratch (no cudaMalloc allowed). Features stored fp16 (aggregation math fp32).
__device__ __align__(16) __half g_Ah[(size_t)N_NODES * HID];  // GEMM outputs / message source
__device__ __align__(16) __half g_Bh[(size_t)N_NODES * HID];  // aggregated features
__device__ __align__(16) float  g_XA[(size_t)N_NODES * 5];    // aggregated raw input (fp32)
__device__ __align__(16) float  g_dinv[N_NODES];
__device__ int   g_cnt[N_NODES];
__device__ int   g_off[N_NODES];     // scan result; k_fill bumps it to segment END
__device__ int   g_bsum[NB_SCAN];
__device__ __align__(8) uint2 g_edge[N_EDGES];   // (src, dinv[src] bits) interleaved

// ---------------- CSR build ----------------
__global__ void k_deg_count(const int* __restrict__ dst) {
    int e = blockIdx.x * blockDim.x + threadIdx.x;
    if (e < N_EDGES) atomicAdd(&g_cnt[dst[e]], 1);
}

// per-block sums of g_cnt + fused dinv computation
__global__ __launch_bounds__(SCAN_B) void k_bsum() {
    __shared__ int sh[SCAN_B];
    int t = threadIdx.x;
    int i = blockIdx.x * SCAN_B + t;
    int c = 0;
    if (i < N_NODES) {
        c = g_cnt[i];
        g_dinv[i] = rsqrtf((float)(c + 1));   // +1 self loop
    }
    sh[t] = c;
    __syncthreads();
    #pragma unroll
    for (int off = SCAN_B / 2; off > 0; off >>= 1) {
        if (t < off) sh[t] += sh[t + off];
        __syncthreads();
    }
    if (t == 0) g_bsum[blockIdx.x] = sh[0];
}

// in-block exclusive scan + inline prefix of block sums (merged bscan)
__global__ __launch_bounds__(SCAN_B) void k_boff() {
    __shared__ int sh[SCAN_B];
    __shared__ int base;
    int t = threadIdx.x;
    if (t < 32) {
        int s = 0;
        for (int i = t; i < (int)blockIdx.x; i += 32) s += g_bsum[i];
        #pragma unroll
        for (int o = 16; o > 0; o >>= 1) s += __shfl_xor_sync(0xffffffffu, s, o);
        if (t == 0) base = s;
    }
    int i = blockIdx.x * SCAN_B + t;
    int v = (i < N_NODES) ? g_cnt[i] : 0;
    sh[t] = v;
    __syncthreads();
    #pragma unroll
    for (int off = 1; off < SCAN_B; off <<= 1) {
        int cur = sh[t];
        int a = (t >= off) ? sh[t - off] : 0;
        __syncthreads();
        sh[t] = cur + a;
        __syncthreads();
    }
    if (i < N_NODES) g_off[i] = base + sh[t] - v;   // exclusive
}

// destructive fill: g_off[d] ends at segment END; start recovered as end - cnt
// 2 edges per thread, int2 index loads, single 8-byte interleaved store per edge
__global__ void k_fill(const int* __restrict__ src, const int* __restrict__ dst) {
    int p = blockIdx.x * blockDim.x + threadIdx.x;
    int e0 = p * 2;
    if (e0 >= N_EDGES) return;
    int2 sv = *(const int2*)(src + e0);
    int2 dv = *(const int2*)(dst + e0);
    {
        int pos = atomicAdd(&g_off[dv.x], 1);
        uint2 ev; ev.x = (u32)sv.x; ev.y = __float_as_uint(g_dinv[sv.x]);
        g_edge[pos] = ev;
    }
    {
        int pos = atomicAdd(&g_off[dv.y], 1);
        uint2 ev; ev.x = (u32)sv.y; ev.y = __float_as_uint(g_dinv[sv.y]);
        g_edge[pos] = ev;
    }
}

// ---------------- layer-1 input aggregation: XA = Â X  (5-wide, fp32) ----------------
__global__ __launch_bounds__(256) void k_agg_x(const float* __restrict__ x) {
    int i = blockIdx.x * blockDim.x + threadIdx.x;
    if (i >= N_NODES) return;
    float dv = g_dinv[i];
    float acc[5];
    #pragma unroll
    for (int k = 0; k < 5; k++) acc[k] = dv * x[(size_t)i * 5 + k];
    int cnt = g_cnt[i];
    int start = g_off[i] - cnt;
    for (int j = 0; j < cnt; j++) {
        uint2 ev = g_edge[start + j];
        int s = (int)ev.x;
        float w = __uint_as_float(ev.y);
        #pragma unroll
        for (int k = 0; k < 5; k++) acc[k] = fmaf(w, x[(size_t)s * 5 + k], acc[k]);
    }
    #pragma unroll
    for (int k = 0; k < 5; k++) g_XA[(size_t)i * 5 + k] = dv * acc[k];
}

// ---------------- aggregation: Bh = Â·Ah + bias  (warp/node; fp16 in/out, fp32 math) ----------------
__global__ __launch_bounds__(256) void k_agg(const float* __restrict__ bias) {
    int g = blockIdx.x * blockDim.x + threadIdx.x;
    int node = g >> 5;
    int lane = g & 31;
    if (node >= N_NODES) return;

    const uint2* __restrict__ A2 = (const uint2*)g_Ah;   // 4 halves per uint2; 32 uint2 per row
    float dv = g_dinv[node];
    uint2 raw = A2[(size_t)node * 32 + lane];
    float2 s0 = __half22float2(*(const half2*)&raw.x);
    float2 s1 = __half22float2(*(const half2*)&raw.y);
    float4 acc;
    acc.x = dv * s0.x; acc.y = dv * s0.y; acc.z = dv * s1.x; acc.w = dv * s1.y;

    int cnt = g_cnt[node];
    int start = g_off[node] - cnt;
    for (int j0 = 0; j0 < cnt; j0 += 32) {
        int  rem = cnt - j0;
        bool ok  = lane < rem;
        uint2 ev = ok ? g_edge[start + j0 + lane] : make_uint2(0u, 0u);
        int m = min(32, rem);
        #pragma unroll 8
        for (int j = 0; j < m; j++) {
            int   sj = (int)__shfl_sync(0xffffffffu, ev.x, j);
            float wj = __uint_as_float(__shfl_sync(0xffffffffu, ev.y, j));
            uint2 r = A2[(size_t)sj * 32 + lane];
            float2 f0 = __half22float2(*(const half2*)&r.x);
            float2 f1 = __half22float2(*(const half2*)&r.y);
            acc.x = fmaf(wj, f0.x, acc.x);
            acc.y = fmaf(wj, f0.y, acc.y);
            acc.z = fmaf(wj, f1.x, acc.z);
            acc.w = fmaf(wj, f1.y, acc.w);
        }
    }
    float4 bb = ((const float4*)bias)[lane];
    float2 o0, o1;
    o0.x = fmaf(dv, acc.x, bb.x);
    o0.y = fmaf(dv, acc.y, bb.y);
    o1.x = fmaf(dv, acc.z, bb.z);
    o1.y = fmaf(dv, acc.w, bb.w);
    half2 p0 = __float22half2_rn(o0);
    half2 p1 = __float22half2_rn(o1);
    uint2 w;
    w.x = *(const u32*)&p0;
    w.y = *(const u32*)&p1;
    ((uint2*)g_Bh)[(size_t)node * 32 + lane] = w;
}

// ---------------- tensor-core GEMM layout constants (128-row CTA tiles) ----------------
#define TILE_ROWS 128
#define A_PITCH 136              // halves (272 B rows)
#define W_PITCH 136
#define SC_PITCH 132             // floats
#define WH_BYTES (HID * W_PITCH * 2)            // 34816 (one W plane)
#define AT_BYTES (TILE_ROWS * A_PITCH * 2)      // 34816
#define L2_SMEM (2 * WH_BYTES + AT_BYTES + (5 * HID + HID) * 4)  // 107008 B
#define L3_SMEM (2 * WH_BYTES + AT_BYTES)                        // 104448 B

// split a float into hi/lo halves: w = hi + lo with |lo| <~ w*2^-12
__device__ __forceinline__ void split_h(float v, __half& hi, __half& lo) {
    hi = __float2half_rn(v);
    lo = __float2half_rn(v - __half2float(hi));
}

__device__ __forceinline__ void load_split_W(__half* Wh, __half* Wl,
                                             const float* __restrict__ W, int tid) {
    const float4* W4 = (const float4*)W;
    #pragma unroll
    for (int i = 0; i < 16; i++) {
        int idx4 = tid + 256 * i;                     // 0..4095
        int k = idx4 >> 5, c0 = (idx4 & 31) * 4;
        float4 v = W4[idx4];
        __half h0, l0, h1, l1, h2, l2, h3, l3;
        split_h(v.x, h0, l0); split_h(v.y, h1, l1);
        split_h(v.z, h2, l2); split_h(v.w, h3, l3);
        __half* wp = Wh + k * W_PITCH + c0;
        wp[0] = h0; wp[1] = h1; wp[2] = h2; wp[3] = h3;
        __half* lp = Wl + k * W_PITCH + c0;
        lp[0] = l0; lp[1] = l1; lp[2] = l2; lp[3] = l3;
    }
}

// shared mainloop + epilogue: warp 'warp' computes rows [warp*16, warp*16+16) x 128 cols
__device__ __forceinline__ void mma_tile_and_store(const __half* Wh, const __half* Wl,
                                                   const __half* At, float* sc,
                                                   __half* gout, int row0, int tid) {
    int warp = tid >> 5;
    wmma::fragment<wmma::accumulator, 16, 16, 16, float> fc[8];
    #pragma unroll
    for (int j = 0; j < 8; j++) wmma::fill_fragment(fc[j], 0.0f);
    #pragma unroll
    for (int k0 = 0; k0 < 8; k0++) {
        wmma::fragment<wmma::matrix_a, 16, 16, 16, __half, wmma::row_major> fa;
        wmma::load_matrix_sync(fa, At + warp * 16 * A_PITCH + k0 * 16, A_PITCH);
        #pragma unroll
        for (int j = 0; j < 8; j++) {
            wmma::fragment<wmma::matrix_b, 16, 16, 16, __half, wmma::row_major> fb;
            wmma::load_matrix_sync(fb, Wh + k0 * 16 * W_PITCH + j * 16, W_PITCH);
            wmma::mma_sync(fc[j], fa, fb, fc[j]);
            wmma::load_matrix_sync(fb, Wl + k0 * 16 * W_PITCH + j * 16, W_PITCH);
            wmma::mma_sync(fc[j], fa, fb, fc[j]);
        }
    }
    __syncthreads();                          // done reading W planes; reuse as fp32 scratch
    #pragma unroll
    for (int j = 0; j < 8; j++)
        wmma::store_matrix_sync(sc + warp * 16 * SC_PITCH + j * 16, fc[j],
                                SC_PITCH, wmma::mem_row_major);
    __syncthreads();
    // convert scratch -> gout (fp16): 128 rows x 32 col-quads, uint2 stores
    #pragma unroll
    for (int i = 0; i < 16; i++) {
        int li = tid + 256 * i;               // 0..4095
        int r = li >> 5, c4 = (li & 31) * 4;
        int grow = row0 + r;
        if (grow < N_NODES) {
            float4 v = *(float4*)&sc[r * SC_PITCH + c4];
            half2 p0 = __floats2half2_rn(v.x, v.y);
            half2 p1 = __floats2half2_rn(v.z, v.w);
            uint2 w;
            w.x = *(const u32*)&p0;
            w.y = *(const u32*)&p1;
            *(uint2*)&gout[(size_t)grow * HID + c4] = w;
        }
    }
}

// ---------------- layer-2 GEMM (fused layer-1 linear): Ah = relu(XA@W1+b1) @ W2 ----------------
__global__ __launch_bounds__(256) void k_gemm_l2(const float* __restrict__ W1,
                                                 const float* __restrict__ b1,
                                                 const float* __restrict__ W2) {
    extern __shared__ char shc[];
    __half* Wh  = (__half*)shc;                       // [128][136] W2 hi
    __half* Wl  = Wh + HID * W_PITCH;                 // [128][136] W2 lo
    __half* At  = Wl + HID * W_PITCH;                 // [128][136] input tile
    float*  W1s = (float*)(At + TILE_ROWS * A_PITCH); // [5][128]
    float*  b1s = W1s + 5 * HID;                      // [128]
    int tid = threadIdx.x;

    load_split_W(Wh, Wl, W2, tid);
    for (int i = tid; i < 5 * HID; i += 256) W1s[i] = W1[i];
    if (tid < HID) b1s[tid] = b1[tid];
    __syncthreads();

    int warp = tid >> 5, lane = tid & 31;
    int row0 = blockIdx.x * TILE_ROWS;

    // prologue: relu(XA@W1 + b1) -> At (fp32 math, fp16 store); warp handles 16 rows
    {
        float4 w1v[5];
        #pragma unroll
        for (int k = 0; k < 5; k++) w1v[k] = ((const float4*)(W1s + k * HID))[lane];
        float4 b1v = ((const float4*)b1s)[lane];
        #pragma unroll
        for (int rr = 0; rr < 16; rr++) {
            int node = row0 + warp * 16 + rr;
            float4 h = make_float4(0.f, 0.f, 0.f, 0.f);
            if (node < N_NODES) {
                const float* xa = g_XA + (size_t)node * 5;
                float xk[5];
                #pragma unroll
                for (int k = 0; k < 5; k++) xk[k] = xa[k];
                h = b1v;
                #pragma unroll
                for (int k = 0; k < 5; k++) {
                    h.x = fmaf(xk[k], w1v[k].x, h.x);
                    h.y = fmaf(xk[k], w1v[k].y, h.y);
                    h.z = fmaf(xk[k], w1v[k].z, h.z);
                    h.w = fmaf(xk[k], w1v[k].w, h.w);
                }
                h.x = fmaxf(h.x, 0.f); h.y = fmaxf(h.y, 0.f);
                h.z = fmaxf(h.z, 0.f); h.w = fmaxf(h.w, 0.f);
            }
            __half* dp = At + (warp * 16 + rr) * A_PITCH + lane * 4;
            *(half2*)dp       = __floats2half2_rn(h.x, h.y);
            *(half2*)(dp + 2) = __floats2half2_rn(h.z, h.w);
        }
    }
    __syncthreads();

    mma_tile_and_store(Wh, Wl, At, (float*)Wh, g_Ah, row0, tid);
}

// ---------------- layer-3 GEMM: Ah = relu(Bh) @ W3  (split-W HMMA) ----------------
__global__ __launch_bounds__(256) void k_gemm_l3(const float* __restrict__ W3) {
    extern __shared__ char shc[];
    __half* Wh = (__half*)shc;                        // [128][136] hi
    __half* Wl = Wh + HID * W_PITCH;                  // [128][136] lo
    __half* At = Wl + HID * W_PITCH;                  // [128][136]
    int tid = threadIdx.x;

    load_split_W(Wh, Wl, W3, tid);

    int row0 = blockIdx.x * TILE_ROWS;
    // tile load: relu(Bh) -> At: 128 rows x 16 uint4 (8 halves each)
    half2 z2 = __floats2half2_rn(0.f, 0.f);
    #pragma unroll
    for (int i = 0; i < 8; i++) {
        int li = tid + 256 * i;               // 0..2047: r = li>>4, q = li&15
        int r = li >> 4, q = li & 15;
        int grow = row0 + r;
        uint4 v = make_uint4(0u, 0u, 0u, 0u);
        if (grow < N_NODES) v = *(const uint4*)&g_Bh[(size_t)grow * HID + q * 8];
        half2 h0 = __hmax2(*(half2*)&v.x, z2);
        half2 h1 = __hmax2(*(half2*)&v.y, z2);
        half2 h2 = __hmax2(*(half2*)&v.z, z2);
        half2 h3 = __hmax2(*(half2*)&v.w, z2);
        __half* dp = At + r * A_PITCH + q * 8;
        *(half2*)(dp + 0) = h0;
        *(half2*)(dp + 2) = h1;
        *(half2*)(dp + 4) = h2;
        *(half2*)(dp + 6) = h3;
    }
    __syncthreads();

    mma_tile_and_store(Wh, Wl, At, (float*)Wh, g_Ah, row0, tid);
}

// ---------------- layer-3 aggregation fused with final FC (fp16 gather, fp32 math) ----------------
__global__ __launch_bounds__(256) void k_agg_final(const float* __restrict__ bias,
                                                   const float* __restrict__ Wfc,
                                                   const float* __restrict__ bfc,
                                                   float* __restrict__ out) {
    int g = blockIdx.x * blockDim.x + threadIdx.x;
    int node = g >> 5;
    int lane = g & 31;
    if (node >= N_NODES) return;

    const uint2* __restrict__ A2 = (const uint2*)g_Ah;
    float dv = g_dinv[node];
    uint2 raw = A2[(size_t)node * 32 + lane];
    float2 s0 = __half22float2(*(const half2*)&raw.x);
    float2 s1 = __half22float2(*(const half2*)&raw.y);
    float4 acc;
    acc.x = dv * s0.x; acc.y = dv * s0.y; acc.z = dv * s1.x; acc.w = dv * s1.y;

    int cnt = g_cnt[node];
    int start = g_off[node] - cnt;
    for (int j0 = 0; j0 < cnt; j0 += 32) {
        int  rem = cnt - j0;
        bool ok  = lane < rem;
        uint2 ev = ok ? g_edge[start + j0 + lane] : make_uint2(0u, 0u);
        int m = min(32, rem);
        #pragma unroll 8
        for (int j = 0; j < m; j++) {
            int   sj = (int)__shfl_sync(0xffffffffu, ev.x, j);
            float wj = __uint_as_float(__shfl_sync(0xffffffffu, ev.y, j));
            uint2 r = A2[(size_t)sj * 32 + lane];
            float2 f0 = __half22float2(*(const half2*)&r.x);
            float2 f1 = __half22float2(*(const half2*)&r.y);
            acc.x = fmaf(wj, f0.x, acc.x);
            acc.y = fmaf(wj, f0.y, acc.y);
            acc.z = fmaf(wj, f1.x, acc.z);
            acc.w = fmaf(wj, f1.y, acc.w);
        }
    }
    float4 bb = ((const float4*)bias)[lane];
    float4 w  = ((const float4*)Wfc)[lane];
    float dot = fmaxf(fmaf(dv, acc.x, bb.x), 0.f) * w.x
              + fmaxf(fmaf(dv, acc.y, bb.y), 0.f) * w.y
              + fmaxf(fmaf(dv, acc.z, bb.z), 0.f) * w.z
              + fmaxf(fmaf(dv, acc.w, bb.w), 0.f) * w.w;
    #pragma unroll
    for (int o = 16; o > 0; o >>= 1) dot += __shfl_xor_sync(0xffffffffu, dot, o);
    if (lane == 0) out[node] = dot + bfc[0];
}

// ---------------- launcher ----------------
extern "C" void kernel_launch(void* const* d_in, const int* in_sizes, int n_in,
                              void* d_out, int out_size) {
    const float* x   = (const float*)d_in[0];
    const int*   ei  = (const int*)  d_in[1];
    const float* W1  = (const float*)d_in[2];
    const float* b1  = (const float*)d_in[3];
    const float* W2  = (const float*)d_in[4];
    const float* b2  = (const float*)d_in[5];
    const float* W3  = (const float*)d_in[6];
    const float* b3  = (const float*)d_in[7];
    const float* Wfc = (const float*)d_in[8];
    const float* bfc = (const float*)d_in[9];
    float* out = (float*)d_out;

    const int* src = ei;
    const int* dst = ei + N_EDGES;

    cudaFuncSetAttribute(k_gemm_l2, cudaFuncAttributeMaxDynamicSharedMemorySize, L2_SMEM);
    cudaFuncSetAttribute(k_gemm_l3, cudaFuncAttributeMaxDynamicSharedMemorySize, L3_SMEM);

    const int T = 256;
    int nb_nodes = (N_NODES + T - 1) / T;
    int nb_edges = (N_EDGES + T - 1) / T;
    int nb_fill  = (N_EDGES / 2 + T - 1) / T;
    int nb_warps = (N_NODES * 32 + T - 1) / T;
    int nb_gemm  = (N_NODES + TILE_ROWS - 1) / TILE_ROWS;

    // CSR build (g_cnt zeroed via async memset — graph-capturable, no alloc)
    void* cntPtr = nullptr;
    cudaGetSymbolAddress(&cntPtr, g_cnt);
    cudaMemsetAsync(cntPtr, 0, N_NODES * sizeof(int));
    k_deg_count<<<nb_edges, T>>>(dst);
    k_bsum     <<<NB_SCAN, SCAN_B>>>();
    k_boff     <<<NB_SCAN, SCAN_B>>>();
    k_fill     <<<nb_fill, T>>>(src, dst);

    // pipeline
    k_agg_x   <<<nb_nodes, T>>>(x);
    k_gemm_l2 <<<nb_gemm, T, L2_SMEM>>>(W1, b1, W2);   // Ah = relu(XA@W1+b1) @ W2  (split-W HMMA)
    k_agg     <<<nb_warps, T>>>(b2);                    // Bh = Â·Ah + b2
    k_gemm_l3 <<<nb_gemm, T, L3_SMEM>>>(W3);            // Ah = relu(Bh) @ W3        (split-W HMMA)
    k_agg_final<<<nb_warps, T>>>(b3, Wfc, bfc, out);    // out = relu(Â·Ah+b3)·Wfc + bfc
}